// round 13
// baseline (speedup 1.0000x reference)
#include <cuda_runtime.h>
#include <cuda_fp16.h>
#include <math.h>

#define N_NODES 200000
#define N_DEST  8192
#define N_EDGE  262144
#define D_MEM   128
#define D_FEAT  128
#define D_EDGE  64
#define D_TIME  32
#define D_MSG   128

// ---------------- scratch (device globals: allocation-free) ------------------
__device__ float g_msg_sum[N_DEST * D_MSG];   // zero-init; dest_kernel re-zeroes
__device__ float g_cnt[N_DEST];
// pre-packed fp16x2 W chunks [chunk][kp][128]:
// 0-7 W_read, 8-14 W_msg, 15-22 W_agg, 23-30 W_upd, 31-34 W_write
__device__ unsigned g_Wf[35 * 2048];

__device__ __forceinline__ int idx_at(const void* p, long long i, int is64) {
    return is64 ? (int)((const long long*)p)[i] : ((const int*)p)[i];
}

// ---------------- fp16 pack / mma ----------------------------------------------
__device__ __forceinline__ unsigned pack_f16(float x0, float x1) {
    unsigned r;
    asm("cvt.rn.f16x2.f32 %0, %1, %2;" : "=r"(r) : "f"(x1), "f"(x0));
    return r;
}

// fp32-accumulator mma (proven; used by dest kernel)
__device__ __forceinline__ void mma_f16(float* c, const unsigned* a, const unsigned* b) {
    asm volatile(
        "mma.sync.aligned.m16n8k16.row.col.f32.f16.f16.f32 "
        "{%0,%1,%2,%3},{%4,%5,%6,%7},{%8,%9},{%0,%1,%2,%3};"
        : "+f"(c[0]), "+f"(c[1]), "+f"(c[2]), "+f"(c[3])
        : "r"(a[0]), "r"(a[1]), "r"(a[2]), "r"(a[3]), "r"(b[0]), "r"(b[1]));
}

// fp16-accumulator mma (edge kernel; 2x rate hypothesis under test)
__device__ __forceinline__ void mma_f16h(unsigned* c, const unsigned* a, const unsigned* b) {
    asm volatile(
        "mma.sync.aligned.m16n8k16.row.col.f16.f16.f16.f16 "
        "{%0,%1},{%2,%3,%4,%5},{%6,%7},{%0,%1};"
        : "+r"(c[0]), "+r"(c[1])
        : "r"(a[0]), "r"(a[1]), "r"(a[2]), "r"(a[3]), "r"(b[0]), "r"(b[1]));
}

// fold per-chunk fp16 partials into fp32 accumulators
__device__ __forceinline__ void fold_h(float acc[2][4][4], unsigned hacc[2][4][2]) {
#pragma unroll
    for (int mf = 0; mf < 2; mf++)
#pragma unroll
        for (int nf = 0; nf < 4; nf++) {
            const float2 f0 = __half22float2(*(__half2*)&hacc[mf][nf][0]);
            const float2 f1 = __half22float2(*(__half2*)&hacc[mf][nf][1]);
            acc[mf][nf][0] += f0.x;
            acc[mf][nf][1] += f0.y;
            acc[mf][nf][2] += f1.x;
            acc[mf][nf][3] += f1.y;
        }
}

// ---------------- cp.async helpers --------------------------------------------
__device__ __forceinline__ void cp16(unsigned dst_smem, const void* src) {
    asm volatile("cp.async.cg.shared.global [%0], [%1], 16;"
                 :: "r"(dst_smem), "l"(src));
}
#define CP_COMMIT() asm volatile("cp.async.commit_group;")
#define CP_WAIT1()  asm volatile("cp.async.wait_group 1;" ::: "memory")

// ---------------- prep: pre-pack ALL weights into fp16x2 ----------------------
__global__ void prep_kernel(const float* __restrict__ W_read,
                            const float* __restrict__ W_msg,
                            const float* __restrict__ W_agg,
                            const float* __restrict__ W_upd,
                            const float* __restrict__ W_write) {
    const int idx = blockIdx.x * blockDim.x + threadIdx.x;
    if (idx >= 35 * 2048) return;
    const int chunk = idx >> 11;
    const int kp = (idx >> 7) & 15;
    const int c = idx & 127;
    const float* W;
    int cl;
    if (chunk < 8)       { W = W_read;  cl = chunk; }
    else if (chunk < 15) { W = W_msg;   cl = chunk - 8; }
    else if (chunk < 23) { W = W_agg;   cl = chunk - 15; }
    else if (chunk < 31) { W = W_upd;   cl = chunk - 23; }
    else                 { W = W_write; cl = chunk - 31; }
    const int row = cl * 32 + 2 * kp;
    g_Wf[idx] = pack_f16(W[row * 128 + c], W[(row + 1) * 128 + c]);
}

// ---------------- mma chunks ----------------------------------------------------
#define PW 136
#define PFA 40   // fp32 staging stride (conflict-free LDS.64)

// fp32-acc chunk over packed A (dest kernel, proven)
__device__ __forceinline__ void mma_k32(const unsigned* __restrict__ Ah, int strideA,
                                        const unsigned* __restrict__ Wh,
                                        int r0, int c0, int gid, int tig,
                                        float acc[2][4][4]) {
#pragma unroll
    for (int half = 0; half < 2; half++) {
        const int kb = half * 8;
        unsigned ah[2][4];
#pragma unroll
        for (int mf = 0; mf < 2; mf++) {
            const int ra = r0 + mf * 16 + gid;
            ah[mf][0] = Ah[ra * strideA + kb + tig];
            ah[mf][1] = Ah[(ra + 8) * strideA + kb + tig];
            ah[mf][2] = Ah[ra * strideA + kb + tig + 4];
            ah[mf][3] = Ah[(ra + 8) * strideA + kb + tig + 4];
        }
#pragma unroll
        for (int nf = 0; nf < 4; nf++) {
            const int col = c0 + nf * 8 + gid;
            unsigned bh[2];
            bh[0] = Wh[(kb + tig) * PW + col];
            bh[1] = Wh[(kb + tig + 4) * PW + col];
#pragma unroll
            for (int mf = 0; mf < 2; mf++) mma_f16(acc[mf][nf], ah[mf], bh);
        }
    }
}

// fp16-acc chunk over packed A; folds into fp32 acc at chunk end (edge ph2)
__device__ __forceinline__ void mma_k32_h(const unsigned* __restrict__ Ah, int strideA,
                                          const unsigned* __restrict__ Wh,
                                          int r0, int c0, int gid, int tig,
                                          float acc[2][4][4]) {
    unsigned hacc[2][4][2];
#pragma unroll
    for (int m = 0; m < 2; m++)
#pragma unroll
        for (int n = 0; n < 4; n++) { hacc[m][n][0] = 0u; hacc[m][n][1] = 0u; }
#pragma unroll
    for (int half = 0; half < 2; half++) {
        const int kb = half * 8;
        unsigned ah[2][4];
#pragma unroll
        for (int mf = 0; mf < 2; mf++) {
            const int ra = r0 + mf * 16 + gid;
            ah[mf][0] = Ah[ra * strideA + kb + tig];
            ah[mf][1] = Ah[(ra + 8) * strideA + kb + tig];
            ah[mf][2] = Ah[ra * strideA + kb + tig + 4];
            ah[mf][3] = Ah[(ra + 8) * strideA + kb + tig + 4];
        }
#pragma unroll
        for (int nf = 0; nf < 4; nf++) {
            const int col = c0 + nf * 8 + gid;
            unsigned bh[2];
            bh[0] = Wh[(kb + tig) * PW + col];
            bh[1] = Wh[(kb + tig + 4) * PW + col];
#pragma unroll
            for (int mf = 0; mf < 2; mf++) mma_f16h(hacc[mf][nf], ah[mf], bh);
        }
    }
    fold_h(acc, hacc);
}

// fp16-acc chunk over fp32 staging A (edge ph1); folds at chunk end
__device__ __forceinline__ void mma_k32_f32h(const float* __restrict__ A,
                                             const unsigned* __restrict__ Wh,
                                             int r0, int c0, int gid, int tig,
                                             float acc[2][4][4]) {
    unsigned hacc[2][4][2];
#pragma unroll
    for (int m = 0; m < 2; m++)
#pragma unroll
        for (int n = 0; n < 4; n++) { hacc[m][n][0] = 0u; hacc[m][n][1] = 0u; }
#pragma unroll
    for (int half = 0; half < 2; half++) {
        const int kf = half * 16 + 2 * tig;
        unsigned ah[2][4];
#pragma unroll
        for (int mf = 0; mf < 2; mf++) {
            const int ra = r0 + mf * 16 + gid;
            const float2 v0 = *(const float2*)(A + ra * PFA + kf);
            const float2 v1 = *(const float2*)(A + (ra + 8) * PFA + kf);
            const float2 v2 = *(const float2*)(A + ra * PFA + kf + 8);
            const float2 v3 = *(const float2*)(A + (ra + 8) * PFA + kf + 8);
            ah[mf][0] = pack_f16(v0.x, v0.y);
            ah[mf][1] = pack_f16(v1.x, v1.y);
            ah[mf][2] = pack_f16(v2.x, v2.y);
            ah[mf][3] = pack_f16(v3.x, v3.y);
        }
        const int kb = half * 8;
#pragma unroll
        for (int nf = 0; nf < 4; nf++) {
            const int col = c0 + nf * 8 + gid;
            unsigned bh[2];
            bh[0] = Wh[(kb + tig) * PW + col];
            bh[1] = Wh[(kb + tig + 4) * PW + col];
#pragma unroll
            for (int mf = 0; mf < 2; mf++) mma_f16h(hacc[mf][nf], ah[mf], bh);
        }
    }
    fold_h(acc, hacc);
}

__device__ __forceinline__ void zacc(float acc[2][4][4]) {
#pragma unroll
    for (int m = 0; m < 2; m++)
#pragma unroll
        for (int n = 0; n < 4; n++)
#pragma unroll
            for (int c = 0; c < 4; c++) acc[m][n][c] = 0.f;
}

// ---------------- edge kernel: depth-2 cp.async + fp16-acc mma ----------------
#define PS 116
#define STRIDE_M 132

#define O_FA0 0
#define O_FA1 2560
#define O_FA2 5120
#define O_W0  7680
#define O_W1  9856
#define O_W2  12032
#define O_ST  14208
#define EDGE_U32 21632
#define EDGE_SMEM (EDGE_U32 * 4)   // 86528 B -> 2 CTAs/SM

__device__ __forceinline__ void flush_seg(int d, int tx, const float* r, float rl) {
    float* p = g_msg_sum + (size_t)d * D_MSG + tx * 4;
    atomicAdd(p + 0, r[0]);
    atomicAdd(p + 1, r[1]);
    atomicAdd(p + 2, r[2]);
    atomicAdd(p + 3, r[3]);
    if (tx == 0) atomicAdd(&g_cnt[d], rl);
}

__global__ __launch_bounds__(256, 2) void edge_kernel(
    const float* __restrict__ node_memory, const float* __restrict__ node_features,
    const float* __restrict__ edge_features, const float* __restrict__ time_encoding,
    const void* __restrict__ node_ids,
    const void* __restrict__ source_ids, const void* __restrict__ edge_ids,
    const void* __restrict__ dest_seg,
    const float* __restrict__ b_read, const float* __restrict__ b_msg,
    float* __restrict__ out) {
    extern __shared__ unsigned su[];
    const float* fpA[3] = {(const float*)(su + O_FA0), (const float*)(su + O_FA1),
                           (const float*)(su + O_FA2)};
    unsigned* const sWp[3] = {su + O_W0, su + O_W1, su + O_W2};
    unsigned* sSh = su + O_ST;
    __shared__ int s_src[64], s_eid[64], s_dst[64];

    const int tid = threadIdx.x;
    const int lane = tid & 31;
    const int warp = tid >> 5;
    const int gid = lane >> 2;
    const int tig = lane & 3;
    const int r0 = (warp >> 2) * 32;
    const int c0 = (warp & 3) * 32;
    const long long ebase = (long long)blockIdx.x * 64;

    const unsigned* nwid = (const unsigned*)node_ids;
    const int is64 = (nwid[1] == 0u && nwid[3] == 0u);

    if (tid < 64) {
        s_src[tid] = idx_at(source_ids, ebase + tid, is64);
        s_eid[tid] = idx_at(edge_ids, ebase + tid, is64);
        s_dst[tid] = idx_at(dest_seg, ebase + tid, is64);
    }
    __syncthreads();

    const int arow = tid >> 2;
    const int aq = tid & 3;
    const int wkp = tid >> 4;
    const int wc8 = (tid & 15) * 8;

    const unsigned smb = (unsigned)__cvta_generic_to_shared(su);
    const unsigned faB[3] = {smb + O_FA0 * 4, smb + O_FA1 * 4, smb + O_FA2 * 4};
    const unsigned whB[3] = {smb + O_W0 * 4, smb + O_W1 * 4, smb + O_W2 * 4};

    auto issueA = [&](int kc, int slot) {
        const float* base = (kc < 4)
            ? node_memory + (size_t)s_src[arow] * D_MEM + kc * 32
            : node_features + (size_t)s_src[arow] * D_FEAT + (kc - 4) * 32;
        const unsigned d = faB[slot] + (arow * PFA + aq * 8) * 4;
        cp16(d, base + aq * 8);
        cp16(d + 16, base + aq * 8 + 4);
    };
    auto issueW = [&](int gc, int slot) {
        const unsigned* src = g_Wf + gc * 2048 + wkp * 128 + wc8;
        const unsigned d = whB[slot] + (wkp * PW + wc8) * 4;
        cp16(d, src);
        cp16(d + 16, src + 4);
    };

    // prologue: two groups in flight
    issueA(0, 0);
    issueW(0, 0);
    CP_COMMIT();
    issueA(1, 1);
    issueW(1, 1);
    CP_COMMIT();

    // prefill stage kpairs [64,112): edge feats, time
    {
        const float4* ef = (const float4*)(edge_features + (size_t)s_eid[arow] * D_EDGE);
#pragma unroll
        for (int j = 0; j < 4; j++) {
            float4 v = ef[aq * 4 + j];
            const int pi = 64 + aq * 8 + 2 * j;
            sSh[arow * PS + pi] = pack_f16(v.x, v.y);
            sSh[arow * PS + pi + 1] = pack_f16(v.z, v.w);
        }
        const float4* tf = (const float4*)(time_encoding + (ebase + arow) * D_TIME);
#pragma unroll
        for (int j = 0; j < 2; j++) {
            float4 v = tf[aq * 2 + j];
            const int pi = 96 + aq * 4 + 2 * j;
            sSh[arow * PS + pi] = pack_f16(v.x, v.y);
            sSh[arow * PS + pi + 1] = pack_f16(v.z, v.w);
        }
    }

    float acc[2][4][4];
    zacc(acc);

    // ---- Phase 1: src_read, K=256, fp16-acc per chunk + fp32 fold ----
    for (int kc = 0; kc < 8; kc++) {
        CP_WAIT1();
        __syncthreads();
        if (kc < 6) {
            issueA(kc + 2, (kc + 2) % 3);
            issueW(kc + 2, (kc + 2) % 3);
        } else {
            issueW(kc + 2, (kc + 2) % 3);
        }
        CP_COMMIT();
        mma_k32_f32h(fpA[kc % 3], sWp[kc % 3], r0, c0, gid, tig, acc);
    }

    // ---- Phase 1 epilogue: bias+relu -> stage kpairs [0,64) ----
#pragma unroll
    for (int mf = 0; mf < 2; mf++) {
        const int ra = r0 + mf * 16 + gid;
#pragma unroll
        for (int nf = 0; nf < 4; nf++) {
            const int col = c0 + nf * 8 + 2 * tig;
            const int pi = col >> 1;
            const float bb0 = b_read[col], bb1 = b_read[col + 1];
            sSh[ra * PS + pi] = pack_f16(fmaxf(acc[mf][nf][0] + bb0, 0.f),
                                         fmaxf(acc[mf][nf][1] + bb1, 0.f));
            sSh[(ra + 8) * PS + pi] = pack_f16(fmaxf(acc[mf][nf][2] + bb0, 0.f),
                                               fmaxf(acc[mf][nf][3] + bb1, 0.f));
        }
    }

    // ---- Phase 2: msgs, K=224, fp16-acc per chunk + fp32 fold ----
    zacc(acc);
    for (int kc = 0; kc < 7; kc++) {
        const int gc = 8 + kc;
        CP_WAIT1();
        __syncthreads();
        if (kc < 5) issueW(gc + 2, (gc + 2) % 3);
        CP_COMMIT();
        mma_k32_h(sSh + kc * 16, PS, sWp[gc % 3], r0, c0, gid, tig, acc);
    }
    __syncthreads();

    // ---- Phase 2 epilogue: msgs -> fp32 msg buffer (aliases staging/W) ----
    float* msg = (float*)su;
#pragma unroll
    for (int mf = 0; mf < 2; mf++) {
        const int ra = r0 + mf * 16 + gid;
#pragma unroll
        for (int nf = 0; nf < 4; nf++) {
            const int col = c0 + nf * 8 + 2 * tig;
            const float b0 = b_msg[col], b1 = b_msg[col + 1];
            msg[ra * STRIDE_M + col]           = fmaxf(acc[mf][nf][0] + b0, 0.f);
            msg[ra * STRIDE_M + col + 1]       = fmaxf(acc[mf][nf][1] + b1, 0.f);
            msg[(ra + 8) * STRIDE_M + col]     = fmaxf(acc[mf][nf][2] + b0, 0.f);
            msg[(ra + 8) * STRIDE_M + col + 1] = fmaxf(acc[mf][nf][3] + b1, 0.f);
        }
    }
    __syncthreads();

    // ---- run-coalesced segment-sum atomics (dest_seg globally sorted) ----
    {
        const int tx = lane;
        const int e0 = warp * 8;
        int curd = s_dst[e0];
        float r[4] = {0.f, 0.f, 0.f, 0.f};
        float rl = 0.f;
#pragma unroll
        for (int i = 0; i < 8; i++) {
            const int e = e0 + i;
            const int d = s_dst[e];
            const float4 v = *(const float4*)(msg + e * STRIDE_M + tx * 4);
            if (d != curd) {
                flush_seg(curd, tx, r, rl);
                curd = d;
                r[0] = r[1] = r[2] = r[3] = 0.f;
                rl = 0.f;
            }
            r[0] += v.x; r[1] += v.y; r[2] += v.z; r[3] += v.w;
            rl += 1.f;
        }
        flush_seg(curd, tx, r, rl);
    }

    // ---- node_memory -> out copy slice ----
    {
        const float4* srcm = (const float4*)node_memory;
        float4* dstm = (float4*)out;
        const long long tot = (long long)N_NODES * D_MEM / 4;
        for (long long i = (long long)blockIdx.x * blockDim.x + tid; i < tot;
             i += (long long)gridDim.x * blockDim.x)
            dstm[i] = srcm[i];
    }
}

// ---------------- dest kernel (proven R10: fp32-acc fp16 MMA) -----------------
#define DPA 20
#define DPS 132
#define DPD 68

#define DO_A 0
#define DO_W 1280
#define DO_S 3456
#define DO_D 11904
#define DEST_U32 16256
#define DEST_SMEM (DEST_U32 * 4)

__global__ __launch_bounds__(256) void dest_kernel(
    const float* __restrict__ node_memory, const float* __restrict__ node_features,
    const void* __restrict__ node_ids,
    const float* __restrict__ b_read, const float* __restrict__ b_agg,
    const float* __restrict__ b_upd, const float* __restrict__ b_write,
    float* __restrict__ out) {
    extern __shared__ unsigned su[];
    unsigned* sA = su + DO_A;
    unsigned* sW = su + DO_W;
    unsigned* sS = su + DO_S;
    unsigned* sD2 = su + DO_D;
    __shared__ int s_nid[64];

    const int tid = threadIdx.x;
    const int lane = tid & 31;
    const int warp = tid >> 5;
    const int gid = lane >> 2;
    const int tig = lane & 3;
    const int r0 = (warp >> 2) * 32;
    const int c0 = (warp & 3) * 32;
    const int rbase = blockIdx.x * 64;

    const unsigned* nwid = (const unsigned*)node_ids;
    const int is64 = (nwid[1] == 0u && nwid[3] == 0u);

    if (tid < 64) s_nid[tid] = idx_at(node_ids, rbase + tid, is64);
    __syncthreads();

    const int arow = tid >> 2;
    const int aq = tid & 3;
    const int wkp = tid >> 4;
    const int wc8 = (tid & 15) * 8;

    float acc[2][4][4];

    // ---- GEMM 1: dst_read, K=256 ----
    zacc(acc);
    for (int kc = 0; kc < 8; kc++) {
        __syncthreads();
        {
            const float* base = (kc < 4)
                ? node_memory + (size_t)s_nid[arow] * D_MEM + kc * 32
                : node_features + (size_t)s_nid[arow] * D_FEAT + (kc - 4) * 32;
            const float4* b4 = (const float4*)base;
            float4 va = b4[aq * 2];
            float4 vb = b4[aq * 2 + 1];
            *(uint4*)(sA + arow * DPA + aq * 4) =
                make_uint4(pack_f16(va.x, va.y), pack_f16(va.z, va.w),
                           pack_f16(vb.x, vb.y), pack_f16(vb.z, vb.w));
        }
        {
            const unsigned* gh = g_Wf + kc * 2048 + wkp * 128 + wc8;
            unsigned* dh = sW + wkp * PW + wc8;
            *(uint4*)dh = *(const uint4*)gh;
            *(uint4*)(dh + 4) = *(const uint4*)(gh + 4);
        }
        __syncthreads();
        mma_k32(sA, DPA, sW, r0, c0, gid, tig, acc);
    }
    __syncthreads();
#pragma unroll
    for (int mf = 0; mf < 2; mf++) {
        const int ra = r0 + mf * 16 + gid;
#pragma unroll
        for (int nf = 0; nf < 4; nf++) {
            const int col = c0 + nf * 8 + 2 * tig;
            const int pi = col >> 1;
            const float bb0 = b_read[col], bb1 = b_read[col + 1];
            unsigned u0 = pack_f16(fmaxf(acc[mf][nf][0] + bb0, 0.f),
                                   fmaxf(acc[mf][nf][1] + bb1, 0.f));
            unsigned u1 = pack_f16(fmaxf(acc[mf][nf][2] + bb0, 0.f),
                                   fmaxf(acc[mf][nf][3] + bb1, 0.f));
            sS[ra * DPS + pi] = u0;       sD2[ra * DPD + pi] = u0;
            sS[(ra + 8) * DPS + pi] = u1; sD2[(ra + 8) * DPD + pi] = u1;
        }
    }

    // msg_mean -> sS kp[64,128); re-zero scratch
    {
        const int dg = rbase + arow;
        const float inv = 1.0f / fmaxf(g_cnt[dg], 1.0f);
        const float4* sp = (const float4*)(g_msg_sum + (size_t)dg * D_MSG + aq * 32);
#pragma unroll
        for (int j4 = 0; j4 < 8; j4++) {
            float4 v = sp[j4];
            const int pi = 64 + aq * 16 + 2 * j4;
            sS[arow * DPS + pi] = pack_f16(v.x * inv, v.y * inv);
            sS[arow * DPS + pi + 1] = pack_f16(v.z * inv, v.w * inv);
        }
        float4 z = {0.f, 0.f, 0.f, 0.f};
        float4* p = (float4*)(g_msg_sum + (size_t)dg * D_MSG + aq * 32);
#pragma unroll
        for (int j4 = 0; j4 < 8; j4++) p[j4] = z;
        if (aq == 0) g_cnt[dg] = 0.f;
    }

    // ---- GEMM 2: agg, K=256 ----
    zacc(acc);
    for (int kc = 0; kc < 8; kc++) {
        __syncthreads();
        {
            const unsigned* gh = g_Wf + (15 + kc) * 2048 + wkp * 128 + wc8;
            unsigned* dh = sW + wkp * PW + wc8;
            *(uint4*)dh = *(const uint4*)gh;
            *(uint4*)(dh + 4) = *(const uint4*)(gh + 4);
        }
        __syncthreads();
        mma_k32(sS + kc * 16, DPS, sW, r0, c0, gid, tig, acc);
    }
    __syncthreads();
#pragma unroll
    for (int mf = 0; mf < 2; mf++) {
        const int ra = r0 + mf * 16 + gid;
#pragma unroll
        for (int nf = 0; nf < 4; nf++) {
            const int col = c0 + nf * 8 + 2 * tig;
            const int pi = col >> 1;
            const float bb0 = b_agg[col], bb1 = b_agg[col + 1];
            sS[ra * DPS + pi] = pack_f16(fmaxf(acc[mf][nf][0] + bb0, 0.f),
                                         fmaxf(acc[mf][nf][1] + bb1, 0.f));
            sS[(ra + 8) * DPS + pi] = pack_f16(fmaxf(acc[mf][nf][2] + bb0, 0.f),
                                               fmaxf(acc[mf][nf][3] + bb1, 0.f));
        }
    }

    // ---- GEMM 3: upd, K=256 (agg from sS, dst_read from sD2) ----
    zacc(acc);
    for (int kc = 0; kc < 8; kc++) {
        __syncthreads();
        {
            const unsigned* gh = g_Wf + (23 + kc) * 2048 + wkp * 128 + wc8;
            unsigned* dh = sW + wkp * PW + wc8;
            *(uint4*)dh = *(const uint4*)gh;
            *(uint4*)(dh + 4) = *(const uint4*)(gh + 4);
        }
        __syncthreads();
        if (kc < 4)
            mma_k32(sS + kc * 16, DPS, sW, r0, c0, gid, tig, acc);
        else
            mma_k32(sD2 + (kc - 4) * 16, DPD, sW, r0, c0, gid, tig, acc);
    }
    __syncthreads();
#pragma unroll
    for (int mf = 0; mf < 2; mf++) {
        const int ra = r0 + mf * 16 + gid;
#pragma unroll
        for (int nf = 0; nf < 4; nf++) {
            const int col = c0 + nf * 8 + 2 * tig;
            const int pi = col >> 1;
            const float bb0 = b_upd[col], bb1 = b_upd[col + 1];
            sS[ra * DPS + pi] = pack_f16(fmaxf(acc[mf][nf][0] + bb0, 0.f),
                                         fmaxf(acc[mf][nf][1] + bb1, 0.f));
            sS[(ra + 8) * DPS + pi] = pack_f16(fmaxf(acc[mf][nf][2] + bb0, 0.f),
                                               fmaxf(acc[mf][nf][3] + bb1, 0.f));
        }
    }

    // ---- GEMM 4: write = tanh(upd @ W_write + b), K=128; scatter ----
    zacc(acc);
    for (int kc = 0; kc < 4; kc++) {
        __syncthreads();
        {
            const unsigned* gh = g_Wf + (31 + kc) * 2048 + wkp * 128 + wc8;
            unsigned* dh = sW + wkp * PW + wc8;
            *(uint4*)dh = *(const uint4*)gh;
            *(uint4*)(dh + 4) = *(const uint4*)(gh + 4);
        }
        __syncthreads();
        mma_k32(sS + kc * 16, DPS, sW, r0, c0, gid, tig, acc);
    }
#pragma unroll
    for (int mf = 0; mf < 2; mf++) {
        const int ra = r0 + mf * 16 + gid;
        const int n0 = s_nid[ra], n1 = s_nid[ra + 8];
#pragma unroll
        for (int nf = 0; nf < 4; nf++) {
            const int col = c0 + nf * 8 + 2 * tig;
            const float bb0 = b_write[col], bb1 = b_write[col + 1];
            float2 o0, o1;
            o0.x = tanhf(acc[mf][nf][0] + bb0);
            o0.y = tanhf(acc[mf][nf][1] + bb1);
            o1.x = tanhf(acc[mf][nf][2] + bb0);
            o1.y = tanhf(acc[mf][nf][3] + bb1);
            *(float2*)(out + (size_t)n0 * D_MEM + col) = o0;
            *(float2*)(out + (size_t)n1 * D_MEM + col) = o1;
        }
    }
}

// ---------------- launch ------------------------------------------------------
extern "C" void kernel_launch(void* const* d_in, const int* in_sizes, int n_in,
                              void* d_out, int out_size) {
    const float* node_memory   = (const float*)d_in[0];
    const float* node_features = (const float*)d_in[1];
    const float* edge_features = (const float*)d_in[2];
    const float* time_encoding = (const float*)d_in[3];
    const void*  node_ids      = d_in[4];
    const void*  source_ids    = d_in[5];
    const void*  edge_ids      = d_in[6];
    const void*  dest_seg      = d_in[7];
    const float* W_read  = (const float*)d_in[8];
    const float* b_read  = (const float*)d_in[9];
    const float* W_msg   = (const float*)d_in[10];
    const float* b_msg   = (const float*)d_in[11];
    const float* W_agg   = (const float*)d_in[12];
    const float* b_agg   = (const float*)d_in[13];
    const float* W_upd   = (const float*)d_in[14];
    const float* b_upd   = (const float*)d_in[15];
    const float* W_write = (const float*)d_in[16];
    const float* b_write = (const float*)d_in[17];
    float* out = (float*)d_out;

    cudaFuncSetAttribute(edge_kernel, cudaFuncAttributeMaxDynamicSharedMemorySize, EDGE_SMEM);
    cudaFuncSetAttribute(dest_kernel, cudaFuncAttributeMaxDynamicSharedMemorySize, DEST_SMEM);

    prep_kernel<<<280, 256>>>(W_read, W_msg, W_agg, W_upd, W_write);

    edge_kernel<<<N_EDGE / 64, 256, EDGE_SMEM>>>(
        node_memory, node_features, edge_features, time_encoding, node_ids,
        source_ids, edge_ids, dest_seg, b_read, b_msg, out);

    dest_kernel<<<N_DEST / 64, 256, DEST_SMEM>>>(
        node_memory, node_features, node_ids,
        b_read, b_agg, b_upd, b_write, out);
}

// round 14
// speedup vs baseline: 1.0129x; 1.0129x over previous
#include <cuda_runtime.h>
#include <cuda_fp16.h>
#include <math.h>

#define N_NODES 200000
#define N_DEST  8192
#define N_EDGE  262144
#define D_MEM   128
#define D_FEAT  128
#define D_EDGE  64
#define D_TIME  32
#define D_MSG   128

// ---------------- scratch (device globals: allocation-free) ------------------
__device__ float g_msg_sum[N_DEST * D_MSG];   // zero-init; dest_kernel re-zeroes
__device__ float g_cnt[N_DEST];
// fp16x2 W chunks for dest kernel: 0-7 read, 8-14 msg, 15-22 agg, 23-30 upd, 31-34 write
__device__ unsigned g_Wf[35 * 2048];
// int8 W images for edge kernel: [15 chunks][128 cols][12 u32 stride(8 used)]
__device__ unsigned g_Wq[15 * 1536];
// per-column W scales: [0,128) W_read, [128,256) W_msg  (scale = colmax/127)
__device__ float g_swv[256];

__device__ __forceinline__ int idx_at(const void* p, long long i, int is64) {
    return is64 ? (int)((const long long*)p)[i] : ((const int*)p)[i];
}

// ---------------- fp16 pack / mma (dest kernel, proven) ------------------------
__device__ __forceinline__ unsigned pack_f16(float x0, float x1) {
    unsigned r;
    asm("cvt.rn.f16x2.f32 %0, %1, %2;" : "=r"(r) : "f"(x1), "f"(x0));
    return r;
}

__device__ __forceinline__ void mma_f16(float* c, const unsigned* a, const unsigned* b) {
    asm volatile(
        "mma.sync.aligned.m16n8k16.row.col.f32.f16.f16.f32 "
        "{%0,%1,%2,%3},{%4,%5,%6,%7},{%8,%9},{%0,%1,%2,%3};"
        : "+f"(c[0]), "+f"(c[1]), "+f"(c[2]), "+f"(c[3])
        : "r"(a[0]), "r"(a[1]), "r"(a[2]), "r"(a[3]), "r"(b[0]), "r"(b[1]));
}

// ---------------- int8 mma + quant helpers (edge kernel) -----------------------
__device__ __forceinline__ void mma_s8(int* c, const unsigned* a, const unsigned* b) {
    asm volatile(
        "mma.sync.aligned.m16n8k32.row.col.s32.s8.s8.s32 "
        "{%0,%1,%2,%3},{%4,%5,%6,%7},{%8,%9},{%0,%1,%2,%3};"
        : "+r"(c[0]), "+r"(c[1]), "+r"(c[2]), "+r"(c[3])
        : "r"(a[0]), "r"(a[1]), "r"(a[2]), "r"(a[3]), "r"(b[0]), "r"(b[1]));
}

// pack 4 floats*inv -> 4 int8 in one u32, byte0 = s0 (lowest k)
__device__ __forceinline__ unsigned quant4(float s0, float s1, float s2, float s3,
                                           float inv) {
    int i0 = __float2int_rn(s0 * inv);
    int i1 = __float2int_rn(s1 * inv);
    int i2 = __float2int_rn(s2 * inv);
    int i3 = __float2int_rn(s3 * inv);
    unsigned t, r;
    asm("cvt.pack.sat.s8.s32.b32 %0, %1, %2, 0;" : "=r"(t) : "r"(i3), "r"(i2));
    asm("cvt.pack.sat.s8.s32.b32 %0, %1, %2, %3;" : "=r"(r) : "r"(i1), "r"(i0), "r"(t));
    return r;
}
// pack 2 floats*inv -> 2 int8 in low 16 bits, byte0 = s0
__device__ __forceinline__ unsigned quant2(float s0, float s1, float inv) {
    int i0 = __float2int_rn(s0 * inv);
    int i1 = __float2int_rn(s1 * inv);
    unsigned r;
    asm("cvt.pack.sat.s8.s32.b32 %0, %1, %2, 0;" : "=r"(r) : "r"(i1), "r"(i0));
    return r;
}

// ---------------- cp.async helpers --------------------------------------------
__device__ __forceinline__ void cp16(unsigned dst_smem, const void* src) {
    asm volatile("cp.async.cg.shared.global [%0], [%1], 16;"
                 :: "r"(dst_smem), "l"(src));
}
#define CP_COMMIT() asm volatile("cp.async.commit_group;")
#define CP_WAIT1()  asm volatile("cp.async.wait_group 1;" ::: "memory")

// ---------------- prep kernels --------------------------------------------------
__global__ void prep_kernel(const float* __restrict__ W_read,
                            const float* __restrict__ W_msg,
                            const float* __restrict__ W_agg,
                            const float* __restrict__ W_upd,
                            const float* __restrict__ W_write) {
    const int idx = blockIdx.x * blockDim.x + threadIdx.x;
    if (idx >= 35 * 2048) return;
    const int chunk = idx >> 11;
    const int kp = (idx >> 7) & 15;
    const int c = idx & 127;
    const float* W;
    int cl;
    if (chunk < 8)       { W = W_read;  cl = chunk; }
    else if (chunk < 15) { W = W_msg;   cl = chunk - 8; }
    else if (chunk < 23) { W = W_agg;   cl = chunk - 15; }
    else if (chunk < 31) { W = W_upd;   cl = chunk - 23; }
    else                 { W = W_write; cl = chunk - 31; }
    const int row = cl * 32 + 2 * kp;
    g_Wf[idx] = pack_f16(W[row * 128 + c], W[(row + 1) * 128 + c]);
}

__global__ void prep_scales(const float* __restrict__ W_read,
                            const float* __restrict__ W_msg) {
    const int t = blockIdx.x * blockDim.x + threadIdx.x;
    if (t >= 256) return;
    float m = 0.f;
    if (t < 128) {
        for (int k = 0; k < 256; k++) m = fmaxf(m, fabsf(W_read[k * 128 + t]));
    } else {
        const int c = t - 128;
        for (int k = 0; k < 224; k++) m = fmaxf(m, fabsf(W_msg[k * 128 + c]));
    }
    g_swv[t] = m * (1.f / 127.f);
}

__global__ void prep_quant(const float* __restrict__ W_read,
                           const float* __restrict__ W_msg) {
    const int idx = blockIdx.x * blockDim.x + threadIdx.x;
    if (idx >= 15 * 1024) return;
    const int chunk = idx >> 10;
    const int rem = idx & 1023;
    const int c = rem >> 3;
    const int kq = rem & 7;
    const float* W;
    float sw;
    int k0;
    if (chunk < 8) { W = W_read; k0 = chunk * 32 + kq * 4; sw = g_swv[c]; }
    else           { W = W_msg;  k0 = (chunk - 8) * 32 + kq * 4; sw = g_swv[128 + c]; }
    const float inv = (sw > 0.f) ? (1.f / sw) : 0.f;
    g_Wq[chunk * 1536 + c * 12 + kq] =
        quant4(W[k0 * 128 + c], W[(k0 + 1) * 128 + c],
               W[(k0 + 2) * 128 + c], W[(k0 + 3) * 128 + c], inv);
}

// ---------------- edge kernel: int8 IMMA, depth-2 cp.async --------------------
#define PFA 48    // fp32 staging row stride (float4 pattern conflict-free: 48%32=16)
#define PWQ 12    // W int8 image per-column stride (12g+t distinct mod 32)
#define PST 60    // stage int8 row stride in u32 (60g+t distinct mod 32)
#define STRIDE_M 132

// smem u32 offsets
#define O_FA0 0        // fp32 A staging: 3 x 64*48
#define O_FA1 3072
#define O_FA2 6144
#define O_WQ0 9216     // W int8: 3 x 1536
#define O_WQ1 10752
#define O_WQ2 12288
#define O_ST  13824    // stage int8: 64*60 = 3840
#define O_SA2 17664    // stage scales: 64*8 = 512
#define EDGE_U32 18176
#define EDGE_SMEM (EDGE_U32 * 4)   // 72704 B -> 2 CTAs/SM
// msg fp32 buffer (8448 u32) aliases staging region [0, 9216)

__device__ __forceinline__ void flush_seg(int d, int tx, const float* r, float rl) {
    float* p = g_msg_sum + (size_t)d * D_MSG + tx * 4;
    atomicAdd(p + 0, r[0]);
    atomicAdd(p + 1, r[1]);
    atomicAdd(p + 2, r[2]);
    atomicAdd(p + 3, r[3]);
    if (tx == 0) atomicAdd(&g_cnt[d], rl);
}

__device__ __forceinline__ void zacc(float acc[2][4][4]) {
#pragma unroll
    for (int m = 0; m < 2; m++)
#pragma unroll
        for (int n = 0; n < 4; n++)
#pragma unroll
            for (int c = 0; c < 4; c++) acc[m][n][c] = 0.f;
}

__device__ __forceinline__ float max4(float4 v) {
    return fmaxf(fmaxf(fabsf(v.x), fabsf(v.y)), fmaxf(fabsf(v.z), fabsf(v.w)));
}

// phase-1 chunk: quantize A in-fragment from fp32 staging, IMMA, fold to fp32
__device__ __forceinline__ void mma_i8_ph1(
    const float* __restrict__ A, const unsigned* __restrict__ Wq,
    const float* __restrict__ swc, int r0, int c0, int gid, int tig,
    float acc[2][4][4]) {
#pragma unroll
    for (int mf = 0; mf < 2; mf++) {
        const float* p0 = A + (r0 + mf * 16 + gid) * PFA + tig * 4;
        const float* p1 = p0 + 8 * PFA;
        const float4 x0 = *(const float4*)p0;
        const float4 x1 = *(const float4*)(p0 + 16);
        const float4 y0 = *(const float4*)p1;
        const float4 y1 = *(const float4*)(p1 + 16);
        float m0 = fmaxf(max4(x0), max4(x1));
        float m1 = fmaxf(max4(y0), max4(y1));
        m0 = fmaxf(m0, __shfl_xor_sync(0xffffffffu, m0, 1));
        m0 = fmaxf(m0, __shfl_xor_sync(0xffffffffu, m0, 2));
        m1 = fmaxf(m1, __shfl_xor_sync(0xffffffffu, m1, 1));
        m1 = fmaxf(m1, __shfl_xor_sync(0xffffffffu, m1, 2));
        const float inv0 = (m0 > 0.f) ? (127.f / m0) : 0.f;
        const float inv1 = (m1 > 0.f) ? (127.f / m1) : 0.f;
        const float sa0 = m0 * (1.f / 127.f);
        const float sa1 = m1 * (1.f / 127.f);
        unsigned a[4];
        a[0] = quant4(x0.x, x0.y, x0.z, x0.w, inv0);
        a[2] = quant4(x1.x, x1.y, x1.z, x1.w, inv0);
        a[1] = quant4(y0.x, y0.y, y0.z, y0.w, inv1);
        a[3] = quant4(y1.x, y1.y, y1.z, y1.w, inv1);
#pragma unroll
        for (int nf = 0; nf < 4; nf++) {
            const int col = c0 + nf * 8 + gid;
            unsigned b[2];
            b[0] = Wq[col * PWQ + tig];
            b[1] = Wq[col * PWQ + 4 + tig];
            int c4[4] = {0, 0, 0, 0};
            mma_s8(c4, a, b);
            acc[mf][nf][0] = fmaf((float)c4[0], sa0 * swc[nf * 2],     acc[mf][nf][0]);
            acc[mf][nf][1] = fmaf((float)c4[1], sa0 * swc[nf * 2 + 1], acc[mf][nf][1]);
            acc[mf][nf][2] = fmaf((float)c4[2], sa1 * swc[nf * 2],     acc[mf][nf][2]);
            acc[mf][nf][3] = fmaf((float)c4[3], sa1 * swc[nf * 2 + 1], acc[mf][nf][3]);
        }
    }
}

// phase-2 chunk: int8 A from stage (+ per-row-chunk scales), IMMA, fold
__device__ __forceinline__ void mma_i8_ph2(
    const unsigned* __restrict__ St, const float* __restrict__ sa2, int kc,
    const unsigned* __restrict__ Wq, const float* __restrict__ swc,
    int r0, int c0, int gid, int tig, float acc[2][4][4]) {
    const int k8 = kc * 8;
#pragma unroll
    for (int mf = 0; mf < 2; mf++) {
        const int r = r0 + mf * 16 + gid;
        unsigned a[4];
        a[0] = St[r * PST + k8 + tig];
        a[2] = St[r * PST + k8 + 4 + tig];
        a[1] = St[(r + 8) * PST + k8 + tig];
        a[3] = St[(r + 8) * PST + k8 + 4 + tig];
        const float sa0 = sa2[r * 8 + kc];
        const float sa1 = sa2[(r + 8) * 8 + kc];
#pragma unroll
        for (int nf = 0; nf < 4; nf++) {
            const int col = c0 + nf * 8 + gid;
            unsigned b[2];
            b[0] = Wq[col * PWQ + tig];
            b[1] = Wq[col * PWQ + 4 + tig];
            int c4[4] = {0, 0, 0, 0};
            mma_s8(c4, a, b);
            acc[mf][nf][0] = fmaf((float)c4[0], sa0 * swc[nf * 2],     acc[mf][nf][0]);
            acc[mf][nf][1] = fmaf((float)c4[1], sa0 * swc[nf * 2 + 1], acc[mf][nf][1]);
            acc[mf][nf][2] = fmaf((float)c4[2], sa1 * swc[nf * 2],     acc[mf][nf][2]);
            acc[mf][nf][3] = fmaf((float)c4[3], sa1 * swc[nf * 2 + 1], acc[mf][nf][3]);
        }
    }
}

__global__ __launch_bounds__(256, 2) void edge_kernel(
    const float* __restrict__ node_memory, const float* __restrict__ node_features,
    const float* __restrict__ edge_features, const float* __restrict__ time_encoding,
    const void* __restrict__ node_ids,
    const void* __restrict__ source_ids, const void* __restrict__ edge_ids,
    const void* __restrict__ dest_seg,
    const float* __restrict__ b_read, const float* __restrict__ b_msg,
    float* __restrict__ out) {
    extern __shared__ unsigned su[];
    const float* fpA[3] = {(const float*)(su + O_FA0), (const float*)(su + O_FA1),
                           (const float*)(su + O_FA2)};
    unsigned* const sWq[3] = {su + O_WQ0, su + O_WQ1, su + O_WQ2};
    unsigned* St = su + O_ST;
    float* sa2s = (float*)(su + O_SA2);
    __shared__ int s_src[64], s_eid[64], s_dst[64];

    const int tid = threadIdx.x;
    const int lane = tid & 31;
    const int warp = tid >> 5;
    const int gid = lane >> 2;
    const int tig = lane & 3;
    const int r0 = (warp >> 2) * 32;
    const int c0 = (warp & 3) * 32;
    const long long ebase = (long long)blockIdx.x * 64;

    const unsigned* nwid = (const unsigned*)node_ids;
    const int is64 = (nwid[1] == 0u && nwid[3] == 0u);

    if (tid < 64) {
        s_src[tid] = idx_at(source_ids, ebase + tid, is64);
        s_eid[tid] = idx_at(edge_ids, ebase + tid, is64);
        s_dst[tid] = idx_at(dest_seg, ebase + tid, is64);
    }
    __syncthreads();

    const int arow = tid >> 2;
    const int aq = tid & 3;

    const unsigned smb = (unsigned)__cvta_generic_to_shared(su);
    const unsigned faB[3] = {smb + O_FA0 * 4, smb + O_FA1 * 4, smb + O_FA2 * 4};
    const unsigned wqB[3] = {smb + O_WQ0 * 4, smb + O_WQ1 * 4, smb + O_WQ2 * 4};

    auto issueA = [&](int kc, int slot) {
        const float* base = (kc < 4)
            ? node_memory + (size_t)s_src[arow] * D_MEM + kc * 32
            : node_features + (size_t)s_src[arow] * D_FEAT + (kc - 4) * 32;
        const unsigned d = faB[slot] + (arow * PFA + aq * 8) * 4;
        cp16(d, base + aq * 8);
        cp16(d + 16, base + aq * 8 + 4);
    };
    auto issueW = [&](int gc, int slot) {
        if (tid < 192) {
            const unsigned* src = g_Wq + gc * 1536 + tid * 8;
            const unsigned d = wqB[slot] + tid * 32;
            cp16(d, src);
            cp16(d + 16, src + 4);
        }
    };

    // per-warp per-phase column scales (8 each)
    float swc1[8], swc2[8];
#pragma unroll
    for (int nf = 0; nf < 4; nf++) {
        const int col = c0 + nf * 8 + 2 * tig;
        swc1[nf * 2] = g_swv[col];
        swc1[nf * 2 + 1] = g_swv[col + 1];
        swc2[nf * 2] = g_swv[128 + col];
        swc2[nf * 2 + 1] = g_swv[128 + col + 1];
    }

    // prologue: two groups in flight
    issueA(0, 0); issueW(0, 0); CP_COMMIT();
    issueA(1, 1); issueW(1, 1); CP_COMMIT();

    // ---- prefill stage k[128,224): edge feats (words 32-47), time (48-55) ----
    {
        const float4* ef = (const float4*)(edge_features + (size_t)s_eid[arow] * D_EDGE);
        float e[16];
#pragma unroll
        for (int j = 0; j < 4; j++) {
            const float4 v = ef[aq * 4 + j];
            e[j * 4] = v.x; e[j * 4 + 1] = v.y; e[j * 4 + 2] = v.z; e[j * 4 + 3] = v.w;
        }
        float m = 0.f;
#pragma unroll
        for (int i = 0; i < 16; i++) m = fmaxf(m, fabsf(e[i]));
        m = fmaxf(m, __shfl_xor_sync(0xffffffffu, m, 1));
        const float inv = (m > 0.f) ? (127.f / m) : 0.f;
        if ((aq & 1) == 0) sa2s[arow * 8 + 4 + (aq >> 1)] = m * (1.f / 127.f);
#pragma unroll
        for (int j = 0; j < 4; j++)
            St[arow * PST + 32 + aq * 4 + j] =
                quant4(e[j * 4], e[j * 4 + 1], e[j * 4 + 2], e[j * 4 + 3], inv);

        const float4* tf = (const float4*)(time_encoding + (ebase + arow) * D_TIME);
        float t[8];
#pragma unroll
        for (int j = 0; j < 2; j++) {
            const float4 v = tf[aq * 2 + j];
            t[j * 4] = v.x; t[j * 4 + 1] = v.y; t[j * 4 + 2] = v.z; t[j * 4 + 3] = v.w;
        }
        float m2 = 0.f;
#pragma unroll
        for (int i = 0; i < 8; i++) m2 = fmaxf(m2, fabsf(t[i]));
        m2 = fmaxf(m2, __shfl_xor_sync(0xffffffffu, m2, 1));
        m2 = fmaxf(m2, __shfl_xor_sync(0xffffffffu, m2, 2));
        const float inv2 = (m2 > 0.f) ? (127.f / m2) : 0.f;
        if (aq == 0) sa2s[arow * 8 + 6] = m2 * (1.f / 127.f);
#pragma unroll
        for (int j = 0; j < 2; j++)
            St[arow * PST + 48 + aq * 2 + j] =
                quant4(t[j * 4], t[j * 4 + 1], t[j * 4 + 2], t[j * 4 + 3], inv2);
    }

    float acc[2][4][4];
    zacc(acc);

    // ---- Phase 1: src_read, K=256, depth-2 pipeline ----
    for (int kc = 0; kc < 8; kc++) {
        CP_WAIT1();
        __syncthreads();
        if (kc < 6) {
            issueA(kc + 2, (kc + 2) % 3);
            issueW(kc + 2, (kc + 2) % 3);
        } else {
            issueW(kc + 2, (kc + 2) % 3);   // phase-2 W chunks 8, 9
        }
        CP_COMMIT();
        mma_i8_ph1(fpA[kc % 3], sWq[kc % 3], swc1, r0, c0, gid, tig, acc);
    }

    // ---- Phase 1 epilogue: bias+relu, quantize -> stage k[0,128) + scales ----
    {
        const int cc = c0 >> 5;   // phase-2 chunk index 0..3
#pragma unroll
        for (int mf = 0; mf < 2; mf++) {
            const int r = r0 + mf * 16 + gid;
            float v0[8], v1[8];
#pragma unroll
            for (int nf = 0; nf < 4; nf++) {
                const int col = c0 + nf * 8 + 2 * tig;
                const float bb0 = b_read[col], bb1 = b_read[col + 1];
                v0[nf * 2]     = fmaxf(acc[mf][nf][0] + bb0, 0.f);
                v0[nf * 2 + 1] = fmaxf(acc[mf][nf][1] + bb1, 0.f);
                v1[nf * 2]     = fmaxf(acc[mf][nf][2] + bb0, 0.f);
                v1[nf * 2 + 1] = fmaxf(acc[mf][nf][3] + bb1, 0.f);
            }
            float m0 = 0.f, m1 = 0.f;
#pragma unroll
            for (int i = 0; i < 8; i++) {
                m0 = fmaxf(m0, v0[i]);
                m1 = fmaxf(m1, v1[i]);
            }
            m0 = fmaxf(m0, __shfl_xor_sync(0xffffffffu, m0, 1));
            m0 = fmaxf(m0, __shfl_xor_sync(0xffffffffu, m0, 2));
            m1 = fmaxf(m1, __shfl_xor_sync(0xffffffffu, m1, 1));
            m1 = fmaxf(m1, __shfl_xor_sync(0xffffffffu, m1, 2));
            const float inv0 = (m0 > 0.f) ? (127.f / m0) : 0.f;
            const float inv1 = (m1 > 0.f) ? (127.f / m1) : 0.f;
            if (tig == 0) {
                sa2s[r * 8 + cc] = m0 * (1.f / 127.f);
                sa2s[(r + 8) * 8 + cc] = m1 * (1.f / 127.f);
            }
#pragma unroll
            for (int nf = 0; nf < 4; nf++) {
                unsigned p0 = quant2(v0[nf * 2], v0[nf * 2 + 1], inv0);
                unsigned p1 = quant2(v1[nf * 2], v1[nf * 2 + 1], inv1);
                const unsigned q0 = __shfl_xor_sync(0xffffffffu, p0, 1);
                const unsigned q1 = __shfl_xor_sync(0xffffffffu, p1, 1);
                if ((tig & 1) == 0) {
                    const int w = cc * 8 + 2 * nf + (tig >> 1);
                    St[r * PST + w] = p0 | (q0 << 16);
                    St[(r + 8) * PST + w] = p1 | (q1 << 16);
                }
            }
        }
    }

    // ---- Phase 2: msgs, K=224, depth-2 W pipeline ----
    zacc(acc);
    for (int kc = 0; kc < 7; kc++) {
        const int gc = 8 + kc;
        CP_WAIT1();
        __syncthreads();   // kc=0: also orders stage/scale writes for all warps
        if (kc < 5) issueW(gc + 2, (gc + 2) % 3);
        CP_COMMIT();
        mma_i8_ph2(St, sa2s, kc, sWq[gc % 3], swc2, r0, c0, gid, tig, acc);
    }
    __syncthreads();

    // ---- Phase 2 epilogue: msgs -> fp32 msg buffer (aliases staging) ----
    float* msg = (float*)su;
#pragma unroll
    for (int mf = 0; mf < 2; mf++) {
        const int ra = r0 + mf * 16 + gid;
#pragma unroll
        for (int nf = 0; nf < 4; nf++) {
            const int col = c0 + nf * 8 + 2 * tig;
            const float b0 = b_msg[col], b1 = b_msg[col + 1];
            msg[ra * STRIDE_M + col]           = fmaxf(acc[mf][nf][0] + b0, 0.f);
            msg[ra * STRIDE_M + col + 1]       = fmaxf(acc[mf][nf][1] + b1, 0.f);
            msg[(ra + 8) * STRIDE_M + col]     = fmaxf(acc[mf][nf][2] + b0, 0.f);
            msg[(ra + 8) * STRIDE_M + col + 1] = fmaxf(acc[mf][nf][3] + b1, 0.f);
        }
    }
    __syncthreads();

    // ---- run-coalesced segment-sum atomics (dest_seg globally sorted) ----
    {
        const int tx = lane;
        const int e0 = warp * 8;
        int curd = s_dst[e0];
        float r[4] = {0.f, 0.f, 0.f, 0.f};
        float rl = 0.f;
#pragma unroll
        for (int i = 0; i < 8; i++) {
            const int e = e0 + i;
            const int d = s_dst[e];
            const float4 v = *(const float4*)(msg + e * STRIDE_M + tx * 4);
            if (d != curd) {
                flush_seg(curd, tx, r, rl);
                curd = d;
                r[0] = r[1] = r[2] = r[3] = 0.f;
                rl = 0.f;
            }
            r[0] += v.x; r[1] += v.y; r[2] += v.z; r[3] += v.w;
            rl += 1.f;
        }
        flush_seg(curd, tx, r, rl);
    }

    // ---- node_memory -> out copy slice ----
    {
        const float4* srcm = (const float4*)node_memory;
        float4* dstm = (float4*)out;
        const long long tot = (long long)N_NODES * D_MEM / 4;
        for (long long i = (long long)blockIdx.x * blockDim.x + tid; i < tot;
             i += (long long)gridDim.x * blockDim.x)
            dstm[i] = srcm[i];
    }
}

// ---------------- dest kernel (proven R10: fp32-acc fp16 MMA) -----------------
#define PW 136
#define DPA 20
#define DPS 132
#define DPD 68

__device__ __forceinline__ void mma_k32(const unsigned* __restrict__ Ah, int strideA,
                                        const unsigned* __restrict__ Wh,
                                        int r0, int c0, int gid, int tig,
                                        float acc[2][4][4]) {
#pragma unroll
    for (int half = 0; half < 2; half++) {
        const int kb = half * 8;
        unsigned ah[2][4];
#pragma unroll
        for (int mf = 0; mf < 2; mf++) {
            const int ra = r0 + mf * 16 + gid;
            ah[mf][0] = Ah[ra * strideA + kb + tig];
            ah[mf][1] = Ah[(ra + 8) * strideA + kb + tig];
            ah[mf][2] = Ah[ra * strideA + kb + tig + 4];
            ah[mf][3] = Ah[(ra + 8) * strideA + kb + tig + 4];
        }
#pragma unroll
        for (int nf = 0; nf < 4; nf++) {
            const int col = c0 + nf * 8 + gid;
            unsigned bh[2];
            bh[0] = Wh[(kb + tig) * PW + col];
            bh[1] = Wh[(kb + tig + 4) * PW + col];
#pragma unroll
            for (int mf = 0; mf < 2; mf++) mma_f16(acc[mf][nf], ah[mf], bh);
        }
    }
}

#define DO_A 0
#define DO_W 1280
#define DO_S 3456
#define DO_D 11904
#define DEST_U32 16256
#define DEST_SMEM (DEST_U32 * 4)

__global__ __launch_bounds__(256) void dest_kernel(
    const float* __restrict__ node_memory, const float* __restrict__ node_features,
    const void* __restrict__ node_ids,
    const float* __restrict__ b_read, const float* __restrict__ b_agg,
    const float* __restrict__ b_upd, const float* __restrict__ b_write,
    float* __restrict__ out) {
    extern __shared__ unsigned su[];
    unsigned* sA = su + DO_A;
    unsigned* sW = su + DO_W;
    unsigned* sS = su + DO_S;
    unsigned* sD2 = su + DO_D;
    __shared__ int s_nid[64];

    const int tid = threadIdx.x;
    const int lane = tid & 31;
    const int warp = tid >> 5;
    const int gid = lane >> 2;
    const int tig = lane & 3;
    const int r0 = (warp >> 2) * 32;
    const int c0 = (warp & 3) * 32;
    const int rbase = blockIdx.x * 64;

    const unsigned* nwid = (const unsigned*)node_ids;
    const int is64 = (nwid[1] == 0u && nwid[3] == 0u);

    if (tid < 64) s_nid[tid] = idx_at(node_ids, rbase + tid, is64);
    __syncthreads();

    const int arow = tid >> 2;
    const int aq = tid & 3;
    const int wkp = tid >> 4;
    const int wc8 = (tid & 15) * 8;

    float acc[2][4][4];

    zacc(acc);
    for (int kc = 0; kc < 8; kc++) {
        __syncthreads();
        {
            const float* base = (kc < 4)
                ? node_memory + (size_t)s_nid[arow] * D_MEM + kc * 32
                : node_features + (size_t)s_nid[arow] * D_FEAT + (kc - 4) * 32;
            const float4* b4 = (const float4*)base;
            float4 va = b4[aq * 2];
            float4 vb = b4[aq * 2 + 1];
            *(uint4*)(sA + arow * DPA + aq * 4) =
                make_uint4(pack_f16(va.x, va.y), pack_f16(va.z, va.w),
                           pack_f16(vb.x, vb.y), pack_f16(vb.z, vb.w));
        }
        {
            const unsigned* gh = g_Wf + kc * 2048 + wkp * 128 + wc8;
            unsigned* dh = sW + wkp * PW + wc8;
            *(uint4*)dh = *(const uint4*)gh;
            *(uint4*)(dh + 4) = *(const uint4*)(gh + 4);
        }
        __syncthreads();
        mma_k32(sA, DPA, sW, r0, c0, gid, tig, acc);
    }
    __syncthreads();
#pragma unroll
    for (int mf = 0; mf < 2; mf++) {
        const int ra = r0 + mf * 16 + gid;
#pragma unroll
        for (int nf = 0; nf < 4; nf++) {
            const int col = c0 + nf * 8 + 2 * tig;
            const int pi = col >> 1;
            const float bb0 = b_read[col], bb1 = b_read[col + 1];
            unsigned u0 = pack_f16(fmaxf(acc[mf][nf][0] + bb0, 0.f),
                                   fmaxf(acc[mf][nf][1] + bb1, 0.f));
            unsigned u1 = pack_f16(fmaxf(acc[mf][nf][2] + bb0, 0.f),
                                   fmaxf(acc[mf][nf][3] + bb1, 0.f));
            sS[ra * DPS + pi] = u0;       sD2[ra * DPD + pi] = u0;
            sS[(ra + 8) * DPS + pi] = u1; sD2[(ra + 8) * DPD + pi] = u1;
        }
    }

    {
        const int dg = rbase + arow;
        const float inv = 1.0f / fmaxf(g_cnt[dg], 1.0f);
        const float4* sp = (const float4*)(g_msg_sum + (size_t)dg * D_MSG + aq * 32);
#pragma unroll
        for (int j4 = 0; j4 < 8; j4++) {
            float4 v = sp[j4];
            const int pi = 64 + aq * 16 + 2 * j4;
            sS[arow * DPS + pi] = pack_f16(v.x * inv, v.y * inv);
            sS[arow * DPS + pi + 1] = pack_f16(v.z * inv, v.w * inv);
        }
        float4 z = {0.f, 0.f, 0.f, 0.f};
        float4* p = (float4*)(g_msg_sum + (size_t)dg * D_MSG + aq * 32);
#pragma unroll
        for (int j4 = 0; j4 < 8; j4++) p[j4] = z;
        if (aq == 0) g_cnt[dg] = 0.f;
    }

    zacc(acc);
    for (int kc = 0; kc < 8; kc++) {
        __syncthreads();
        {
            const unsigned* gh = g_Wf + (15 + kc) * 2048 + wkp * 128 + wc8;
            unsigned* dh = sW + wkp * PW + wc8;
            *(uint4*)dh = *(const uint4*)gh;
            *(uint4*)(dh + 4) = *(const uint4*)(gh + 4);
        }
        __syncthreads();
        mma_k32(sS + kc * 16, DPS, sW, r0, c0, gid, tig, acc);
    }
    __syncthreads();
#pragma unroll
    for (int mf = 0; mf < 2; mf++) {
        const int ra = r0 + mf * 16 + gid;
#pragma unroll
        for (int nf = 0; nf < 4; nf++) {
            const int col = c0 + nf * 8 + 2 * tig;
            const int pi = col >> 1;
            const float bb0 = b_agg[col], bb1 = b_agg[col + 1];
            sS[ra * DPS + pi] = pack_f16(fmaxf(acc[mf][nf][0] + bb0, 0.f),
                                         fmaxf(acc[mf][nf][1] + bb1, 0.f));
            sS[(ra + 8) * DPS + pi] = pack_f16(fmaxf(acc[mf][nf][2] + bb0, 0.f),
                                               fmaxf(acc[mf][nf][3] + bb1, 0.f));
        }
    }

    zacc(acc);
    for (int kc = 0; kc < 8; kc++) {
        __syncthreads();
        {
            const unsigned* gh = g_Wf + (23 + kc) * 2048 + wkp * 128 + wc8;
            unsigned* dh = sW + wkp * PW + wc8;
            *(uint4*)dh = *(const uint4*)gh;
            *(uint4*)(dh + 4) = *(const uint4*)(gh + 4);
        }
        __syncthreads();
        if (kc < 4)
            mma_k32(sS + kc * 16, DPS, sW, r0, c0, gid, tig, acc);
        else
            mma_k32(sD2 + (kc - 4) * 16, DPD, sW, r0, c0, gid, tig, acc);
    }
    __syncthreads();
#pragma unroll
    for (int mf = 0; mf < 2; mf++) {
        const int ra = r0 + mf * 16 + gid;
#pragma unroll
        for (int nf = 0; nf < 4; nf++) {
            const int col = c0 + nf * 8 + 2 * tig;
            const int pi = col >> 1;
            const float bb0 = b_upd[col], bb1 = b_upd[col + 1];
            sS[ra * DPS + pi] = pack_f16(fmaxf(acc[mf][nf][0] + bb0, 0.f),
                                         fmaxf(acc[mf][nf][1] + bb1, 0.f));
            sS[(ra + 8) * DPS + pi] = pack_f16(fmaxf(acc[mf][nf][2] + bb0, 0.f),
                                               fmaxf(acc[mf][nf][3] + bb1, 0.f));
        }
    }

    zacc(acc);
    for (int kc = 0; kc < 4; kc++) {
        __syncthreads();
        {
            const unsigned* gh = g_Wf + (31 + kc) * 2048 + wkp * 128 + wc8;
            unsigned* dh = sW + wkp * PW + wc8;
            *(uint4*)dh = *(const uint4*)gh;
            *(uint4*)(dh + 4) = *(const uint4*)(gh + 4);
        }
        __syncthreads();
        mma_k32(sS + kc * 16, DPS, sW, r0, c0, gid, tig, acc);
    }
#pragma unroll
    for (int mf = 0; mf < 2; mf++) {
        const int ra = r0 + mf * 16 + gid;
        const int n0 = s_nid[ra], n1 = s_nid[ra + 8];
#pragma unroll
        for (int nf = 0; nf < 4; nf++) {
            const int col = c0 + nf * 8 + 2 * tig;
            const float bb0 = b_write[col], bb1 = b_write[col + 1];
            float2 o0, o1;
            o0.x = tanhf(acc[mf][nf][0] + bb0);
            o0.y = tanhf(acc[mf][nf][1] + bb1);
            o1.x = tanhf(acc[mf][nf][2] + bb0);
            o1.y = tanhf(acc[mf][nf][3] + bb1);
            *(float2*)(out + (size_t)n0 * D_MEM + col) = o0;
            *(float2*)(out + (size_t)n1 * D_MEM + col) = o1;
        }
    }
}

// ---------------- launch ------------------------------------------------------
extern "C" void kernel_launch(void* const* d_in, const int* in_sizes, int n_in,
                              void* d_out, int out_size) {
    const float* node_memory   = (const float*)d_in[0];
    const float* node_features = (const float*)d_in[1];
    const float* edge_features = (const float*)d_in[2];
    const float* time_encoding = (const float*)d_in[3];
    const void*  node_ids      = d_in[4];
    const void*  source_ids    = d_in[5];
    const void*  edge_ids      = d_in[6];
    const void*  dest_seg      = d_in[7];
    const float* W_read  = (const float*)d_in[8];
    const float* b_read  = (const float*)d_in[9];
    const float* W_msg   = (const float*)d_in[10];
    const float* b_msg   = (const float*)d_in[11];
    const float* W_agg   = (const float*)d_in[12];
    const float* b_agg   = (const float*)d_in[13];
    const float* W_upd   = (const float*)d_in[14];
    const float* b_upd   = (const float*)d_in[15];
    const float* W_write = (const float*)d_in[16];
    const float* b_write = (const float*)d_in[17];
    float* out = (float*)d_out;

    cudaFuncSetAttribute(edge_kernel, cudaFuncAttributeMaxDynamicSharedMemorySize, EDGE_SMEM);
    cudaFuncSetAttribute(dest_kernel, cudaFuncAttributeMaxDynamicSharedMemorySize, DEST_SMEM);

    prep_kernel<<<280, 256>>>(W_read, W_msg, W_agg, W_upd, W_write);
    prep_scales<<<1, 256>>>(W_read, W_msg);
    prep_quant<<<60, 256>>>(W_read, W_msg);

    edge_kernel<<<N_EDGE / 64, 256, EDGE_SMEM>>>(
        node_memory, node_features, edge_features, time_encoding, node_ids,
        source_ids, edge_ids, dest_seg, b_read, b_msg, out);

    dest_kernel<<<N_DEST / 64, 256, DEST_SMEM>>>(
        node_memory, node_features, node_ids,
        b_read, b_agg, b_upd, b_write, out);
}

// round 15
// speedup vs baseline: 1.7419x; 1.7197x over previous
#include <cuda_runtime.h>
#include <cuda_fp16.h>
#include <math.h>

#define N_NODES 200000
#define N_DEST  8192
#define N_EDGE  262144
#define D_MEM   128
#define D_FEAT  128
#define D_EDGE  64
#define D_TIME  32
#define D_MSG   128

// ---------------- scratch (device globals: allocation-free) ------------------
__device__ float g_msg_sum[N_DEST * D_MSG];   // zero-init; dest_kernel re-zeroes
__device__ float g_cnt[N_DEST];
// pre-packed fp16x2 W chunks [chunk][kp][128]:
// 0-7 W_read, 8-14 W_msg, 15-22 W_agg, 23-30 W_upd, 31-34 W_write
__device__ unsigned g_Wf[35 * 2048];

__device__ __forceinline__ int idx_at(const void* p, long long i, int is64) {
    return is64 ? (int)((const long long*)p)[i] : ((const int*)p)[i];
}

// ---------------- fp16 pack / mma ----------------------------------------------
__device__ __forceinline__ unsigned pack_f16(float x0, float x1) {
    unsigned r;
    asm("cvt.rn.f16x2.f32 %0, %1, %2;" : "=r"(r) : "f"(x1), "f"(x0));
    return r;
}

__device__ __forceinline__ void mma_f16(float* c, const unsigned* a, const unsigned* b) {
    asm volatile(
        "mma.sync.aligned.m16n8k16.row.col.f32.f16.f16.f32 "
        "{%0,%1,%2,%3},{%4,%5,%6,%7},{%8,%9},{%0,%1,%2,%3};"
        : "+f"(c[0]), "+f"(c[1]), "+f"(c[2]), "+f"(c[3])
        : "r"(a[0]), "r"(a[1]), "r"(a[2]), "r"(a[3]), "r"(b[0]), "r"(b[1]));
}

// ---------------- cp.async helpers --------------------------------------------
__device__ __forceinline__ void cp16(unsigned dst_smem, const void* src) {
    asm volatile("cp.async.cg.shared.global [%0], [%1], 16;"
                 :: "r"(dst_smem), "l"(src));
}
#define CP_COMMIT() asm volatile("cp.async.commit_group;")
#define CP_WAIT1()  asm volatile("cp.async.wait_group 1;" ::: "memory")

// ---------------- prep: pre-pack ALL weights into fp16x2 ----------------------
__global__ void prep_kernel(const float* __restrict__ W_read,
                            const float* __restrict__ W_msg,
                            const float* __restrict__ W_agg,
                            const float* __restrict__ W_upd,
                            const float* __restrict__ W_write) {
    const int idx = blockIdx.x * blockDim.x + threadIdx.x;
    if (idx >= 35 * 2048) return;
    const int chunk = idx >> 11;
    const int kp = (idx >> 7) & 15;
    const int c = idx & 127;
    const float* W;
    int cl;
    if (chunk < 8)       { W = W_read;  cl = chunk; }
    else if (chunk < 15) { W = W_msg;   cl = chunk - 8; }
    else if (chunk < 23) { W = W_agg;   cl = chunk - 15; }
    else if (chunk < 31) { W = W_upd;   cl = chunk - 23; }
    else                 { W = W_write; cl = chunk - 31; }
    const int row = cl * 32 + 2 * kp;
    g_Wf[idx] = pack_f16(W[row * 128 + c], W[(row + 1) * 128 + c]);
}

// ---------------- shared mma chunks --------------------------------------------
#define PW 136
#define PFA 40   // fp32 staging stride (conflict-free LDS.64)

// fp32-acc chunk over packed fp16 A
__device__ __forceinline__ void mma_k32(const unsigned* __restrict__ Ah, int strideA,
                                        const unsigned* __restrict__ Wh,
                                        int r0, int c0, int gid, int tig,
                                        float acc[2][4][4]) {
#pragma unroll
    for (int half = 0; half < 2; half++) {
        const int kb = half * 8;
        unsigned ah[2][4];
#pragma unroll
        for (int mf = 0; mf < 2; mf++) {
            const int ra = r0 + mf * 16 + gid;
            ah[mf][0] = Ah[ra * strideA + kb + tig];
            ah[mf][1] = Ah[(ra + 8) * strideA + kb + tig];
            ah[mf][2] = Ah[ra * strideA + kb + tig + 4];
            ah[mf][3] = Ah[(ra + 8) * strideA + kb + tig + 4];
        }
#pragma unroll
        for (int nf = 0; nf < 4; nf++) {
            const int col = c0 + nf * 8 + gid;
            unsigned bh[2];
            bh[0] = Wh[(kb + tig) * PW + col];
            bh[1] = Wh[(kb + tig + 4) * PW + col];
#pragma unroll
            for (int mf = 0; mf < 2; mf++) mma_f16(acc[mf][nf], ah[mf], bh);
        }
    }
}

// fp32-acc chunk over fp32 staging A (fragments cvt'd on load)
__device__ __forceinline__ void mma_k32_f32(const float* __restrict__ A,
                                            const unsigned* __restrict__ Wh,
                                            int r0, int c0, int gid, int tig,
                                            float acc[2][4][4]) {
#pragma unroll
    for (int half = 0; half < 2; half++) {
        const int kf = half * 16 + 2 * tig;
        unsigned ah[2][4];
#pragma unroll
        for (int mf = 0; mf < 2; mf++) {
            const int ra = r0 + mf * 16 + gid;
            const float2 v0 = *(const float2*)(A + ra * PFA + kf);
            const float2 v1 = *(const float2*)(A + (ra + 8) * PFA + kf);
            const float2 v2 = *(const float2*)(A + ra * PFA + kf + 8);
            const float2 v3 = *(const float2*)(A + (ra + 8) * PFA + kf + 8);
            ah[mf][0] = pack_f16(v0.x, v0.y);
            ah[mf][1] = pack_f16(v1.x, v1.y);
            ah[mf][2] = pack_f16(v2.x, v2.y);
            ah[mf][3] = pack_f16(v3.x, v3.y);
        }
        const int kb = half * 8;
#pragma unroll
        for (int nf = 0; nf < 4; nf++) {
            const int col = c0 + nf * 8 + gid;
            unsigned bh[2];
            bh[0] = Wh[(kb + tig) * PW + col];
            bh[1] = Wh[(kb + tig + 4) * PW + col];
#pragma unroll
            for (int mf = 0; mf < 2; mf++) mma_f16(acc[mf][nf], ah[mf], bh);
        }
    }
}

__device__ __forceinline__ void zacc(float acc[2][4][4]) {
#pragma unroll
    for (int m = 0; m < 2; m++)
#pragma unroll
        for (int n = 0; n < 4; n++)
#pragma unroll
            for (int c = 0; c < 4; c++) acc[m][n][c] = 0.f;
}

// ---------------- edge kernel (R12 exact: depth-2 cp.async, fp32-acc) ---------
#define PS 116
#define STRIDE_M 132

#define O_FA0 0
#define O_FA1 2560
#define O_FA2 5120
#define O_W0  7680
#define O_W1  9856
#define O_W2  12032
#define O_ST  14208
#define EDGE_U32 21632
#define EDGE_SMEM (EDGE_U32 * 4)   // 86528 B -> 2 CTAs/SM

__device__ __forceinline__ void flush_seg(int d, int tx, const float* r, float rl) {
    float* p = g_msg_sum + (size_t)d * D_MSG + tx * 4;
    atomicAdd(p + 0, r[0]);
    atomicAdd(p + 1, r[1]);
    atomicAdd(p + 2, r[2]);
    atomicAdd(p + 3, r[3]);
    if (tx == 0) atomicAdd(&g_cnt[d], rl);
}

__global__ __launch_bounds__(256, 2) void edge_kernel(
    const float* __restrict__ node_memory, const float* __restrict__ node_features,
    const float* __restrict__ edge_features, const float* __restrict__ time_encoding,
    const void* __restrict__ node_ids,
    const void* __restrict__ source_ids, const void* __restrict__ edge_ids,
    const void* __restrict__ dest_seg,
    const float* __restrict__ b_read, const float* __restrict__ b_msg,
    float* __restrict__ out) {
    extern __shared__ unsigned su[];
    const float* fpA[3] = {(const float*)(su + O_FA0), (const float*)(su + O_FA1),
                           (const float*)(su + O_FA2)};
    unsigned* const sWp[3] = {su + O_W0, su + O_W1, su + O_W2};
    unsigned* sSh = su + O_ST;
    __shared__ int s_src[64], s_eid[64], s_dst[64];

    const int tid = threadIdx.x;
    const int lane = tid & 31;
    const int warp = tid >> 5;
    const int gid = lane >> 2;
    const int tig = lane & 3;
    const int r0 = (warp >> 2) * 32;
    const int c0 = (warp & 3) * 32;
    const long long ebase = (long long)blockIdx.x * 64;

    const unsigned* nwid = (const unsigned*)node_ids;
    const int is64 = (nwid[1] == 0u && nwid[3] == 0u);

    if (tid < 64) {
        s_src[tid] = idx_at(source_ids, ebase + tid, is64);
        s_eid[tid] = idx_at(edge_ids, ebase + tid, is64);
        s_dst[tid] = idx_at(dest_seg, ebase + tid, is64);
    }
    __syncthreads();

    const int arow = tid >> 2;
    const int aq = tid & 3;
    const int wkp = tid >> 4;
    const int wc8 = (tid & 15) * 8;

    const unsigned smb = (unsigned)__cvta_generic_to_shared(su);
    const unsigned faB[3] = {smb + O_FA0 * 4, smb + O_FA1 * 4, smb + O_FA2 * 4};
    const unsigned whB[3] = {smb + O_W0 * 4, smb + O_W1 * 4, smb + O_W2 * 4};

    auto issueA = [&](int kc, int slot) {
        const float* base = (kc < 4)
            ? node_memory + (size_t)s_src[arow] * D_MEM + kc * 32
            : node_features + (size_t)s_src[arow] * D_FEAT + (kc - 4) * 32;
        const unsigned d = faB[slot] + (arow * PFA + aq * 8) * 4;
        cp16(d, base + aq * 8);
        cp16(d + 16, base + aq * 8 + 4);
    };
    auto issueW = [&](int gc, int slot) {
        const unsigned* src = g_Wf + gc * 2048 + wkp * 128 + wc8;
        const unsigned d = whB[slot] + (wkp * PW + wc8) * 4;
        cp16(d, src);
        cp16(d + 16, src + 4);
    };

    issueA(0, 0);
    issueW(0, 0);
    CP_COMMIT();
    issueA(1, 1);
    issueW(1, 1);
    CP_COMMIT();

    // prefill stage kpairs [64,112): edge feats, time
    {
        const float4* ef = (const float4*)(edge_features + (size_t)s_eid[arow] * D_EDGE);
#pragma unroll
        for (int j = 0; j < 4; j++) {
            float4 v = ef[aq * 4 + j];
            const int pi = 64 + aq * 8 + 2 * j;
            sSh[arow * PS + pi] = pack_f16(v.x, v.y);
            sSh[arow * PS + pi + 1] = pack_f16(v.z, v.w);
        }
        const float4* tf = (const float4*)(time_encoding + (ebase + arow) * D_TIME);
#pragma unroll
        for (int j = 0; j < 2; j++) {
            float4 v = tf[aq * 2 + j];
            const int pi = 96 + aq * 4 + 2 * j;
            sSh[arow * PS + pi] = pack_f16(v.x, v.y);
            sSh[arow * PS + pi + 1] = pack_f16(v.z, v.w);
        }
    }

    float acc[2][4][4];
    zacc(acc);

    // ---- Phase 1: src_read, K=256, depth-2 pipeline ----
    for (int kc = 0; kc < 8; kc++) {
        CP_WAIT1();
        __syncthreads();
        if (kc < 6) {
            issueA(kc + 2, (kc + 2) % 3);
            issueW(kc + 2, (kc + 2) % 3);
        } else {
            issueW(kc + 2, (kc + 2) % 3);   // phase-2 W chunks 8, 9
        }
        CP_COMMIT();
        mma_k32_f32(fpA[kc % 3], sWp[kc % 3], r0, c0, gid, tig, acc);
    }

    // ---- Phase 1 epilogue: bias+relu -> stage kpairs [0,64) ----
#pragma unroll
    for (int mf = 0; mf < 2; mf++) {
        const int ra = r0 + mf * 16 + gid;
#pragma unroll
        for (int nf = 0; nf < 4; nf++) {
            const int col = c0 + nf * 8 + 2 * tig;
            const int pi = col >> 1;
            const float bb0 = b_read[col], bb1 = b_read[col + 1];
            sSh[ra * PS + pi] = pack_f16(fmaxf(acc[mf][nf][0] + bb0, 0.f),
                                         fmaxf(acc[mf][nf][1] + bb1, 0.f));
            sSh[(ra + 8) * PS + pi] = pack_f16(fmaxf(acc[mf][nf][2] + bb0, 0.f),
                                               fmaxf(acc[mf][nf][3] + bb1, 0.f));
        }
    }

    // ---- Phase 2: msgs, K=224, W depth-2 ----
    zacc(acc);
    for (int kc = 0; kc < 7; kc++) {
        const int gc = 8 + kc;
        CP_WAIT1();
        __syncthreads();
        if (kc < 5) issueW(gc + 2, (gc + 2) % 3);
        CP_COMMIT();
        mma_k32(sSh + kc * 16, PS, sWp[gc % 3], r0, c0, gid, tig, acc);
    }
    __syncthreads();

    // ---- Phase 2 epilogue: msgs -> fp32 msg buffer (aliases staging/W) ----
    float* msg = (float*)su;
#pragma unroll
    for (int mf = 0; mf < 2; mf++) {
        const int ra = r0 + mf * 16 + gid;
#pragma unroll
        for (int nf = 0; nf < 4; nf++) {
            const int col = c0 + nf * 8 + 2 * tig;
            const float b0 = b_msg[col], b1 = b_msg[col + 1];
            msg[ra * STRIDE_M + col]           = fmaxf(acc[mf][nf][0] + b0, 0.f);
            msg[ra * STRIDE_M + col + 1]       = fmaxf(acc[mf][nf][1] + b1, 0.f);
            msg[(ra + 8) * STRIDE_M + col]     = fmaxf(acc[mf][nf][2] + b0, 0.f);
            msg[(ra + 8) * STRIDE_M + col + 1] = fmaxf(acc[mf][nf][3] + b1, 0.f);
        }
    }
    __syncthreads();

    // ---- run-coalesced segment-sum atomics (dest_seg globally sorted) ----
    {
        const int tx = lane;
        const int e0 = warp * 8;
        int curd = s_dst[e0];
        float r[4] = {0.f, 0.f, 0.f, 0.f};
        float rl = 0.f;
#pragma unroll
        for (int i = 0; i < 8; i++) {
            const int e = e0 + i;
            const int d = s_dst[e];
            const float4 v = *(const float4*)(msg + e * STRIDE_M + tx * 4);
            if (d != curd) {
                flush_seg(curd, tx, r, rl);
                curd = d;
                r[0] = r[1] = r[2] = r[3] = 0.f;
                rl = 0.f;
            }
            r[0] += v.x; r[1] += v.y; r[2] += v.z; r[3] += v.w;
            rl += 1.f;
        }
        flush_seg(curd, tx, r, rl);
    }

    // ---- node_memory -> out copy slice ----
    {
        const float4* srcm = (const float4*)node_memory;
        float4* dstm = (float4*)out;
        const long long tot = (long long)N_NODES * D_MEM / 4;
        for (long long i = (long long)blockIdx.x * blockDim.x + tid; i < tot;
             i += (long long)gridDim.x * blockDim.x)
            dstm[i] = srcm[i];
    }
}

// ---------------- dest kernel: unified 28-chunk cp.async pipeline -------------
#define DPS 132
#define DPD 68

#define DN_FA0 0        // fp32 A staging: 3 x 64*40
#define DN_FA1 2560
#define DN_FA2 5120
#define DN_W0  7680     // W: 3 x 16*136
#define DN_W1  9856
#define DN_W2  12032
#define DN_S   14208    // sS: 64*132 = 8448
#define DN_D   22656    // sD2: 64*68 = 4352
#define DEST_U32 27008
#define DEST_SMEM (DEST_U32 * 4)   // 108032 B -> 1 CTA/SM (1 wave anyway)

__global__ __launch_bounds__(256, 1) void dest_kernel(
    const float* __restrict__ node_memory, const float* __restrict__ node_features,
    const void* __restrict__ node_ids,
    const float* __restrict__ b_read, const float* __restrict__ b_agg,
    const float* __restrict__ b_upd, const float* __restrict__ b_write,
    float* __restrict__ out) {
    extern __shared__ unsigned su[];
    const float* fpA[3] = {(const float*)(su + DN_FA0), (const float*)(su + DN_FA1),
                           (const float*)(su + DN_FA2)};
    unsigned* const sWp[3] = {su + DN_W0, su + DN_W1, su + DN_W2};
    unsigned* sS = su + DN_S;
    unsigned* sD2 = su + DN_D;
    __shared__ int s_nid[64];

    const int tid = threadIdx.x;
    const int lane = tid & 31;
    const int warp = tid >> 5;
    const int gid = lane >> 2;
    const int tig = lane & 3;
    const int r0 = (warp >> 2) * 32;
    const int c0 = (warp & 3) * 32;
    const int rbase = blockIdx.x * 64;

    const unsigned* nwid = (const unsigned*)node_ids;
    const int is64 = (nwid[1] == 0u && nwid[3] == 0u);

    if (tid < 64) s_nid[tid] = idx_at(node_ids, rbase + tid, is64);
    __syncthreads();

    const int arow = tid >> 2;
    const int aq = tid & 3;
    const int wkp = tid >> 4;
    const int wc8 = (tid & 15) * 8;

    const unsigned smb = (unsigned)__cvta_generic_to_shared(su);
    const unsigned faB[3] = {smb + DN_FA0 * 4, smb + DN_FA1 * 4, smb + DN_FA2 * 4};
    const unsigned whB[3] = {smb + DN_W0 * 4, smb + DN_W1 * 4, smb + DN_W2 * 4};

    auto issueA = [&](int kc) {
        const float* base = (kc < 4)
            ? node_memory + (size_t)s_nid[arow] * D_MEM + kc * 32
            : node_features + (size_t)s_nid[arow] * D_FEAT + (kc - 4) * 32;
        const unsigned d = faB[kc % 3] + (arow * PFA + aq * 8) * 4;
        cp16(d, base + aq * 8);
        cp16(d + 16, base + aq * 8 + 4);
    };
    // W sequence chunk i (0..27) -> g_Wf chunk: 0-7, 15-22, 23-30, 31-34
    auto issueWd = [&](int i) {
        if (i >= 28) return;
        const int gc = (i < 8) ? i : i + 7;
        const unsigned* src = g_Wf + gc * 2048 + wkp * 128 + wc8;
        const unsigned d = whB[i % 3] + (wkp * PW + wc8) * 4;
        cp16(d, src);
        cp16(d + 16, src + 4);
    };

    // prologue: groups 0 and 1 (A0+W0, A1+W1)
    issueA(0); issueWd(0); CP_COMMIT();
    issueA(1); issueWd(1); CP_COMMIT();

    float acc[2][4][4];

    // ---- GEMM 1: dst_read, K=256 (pipeline chunks 0-7) ----
    zacc(acc);
    for (int kc = 0; kc < 8; kc++) {
        CP_WAIT1();
        __syncthreads();
        if (kc < 6) issueA(kc + 2);
        issueWd(kc + 2);
        CP_COMMIT();
        mma_k32_f32(fpA[kc % 3], sWp[kc % 3], r0, c0, gid, tig, acc);
    }
    __syncthreads();
    // epilogue: dst_read -> sS kp[0,64) and sD2
#pragma unroll
    for (int mf = 0; mf < 2; mf++) {
        const int ra = r0 + mf * 16 + gid;
#pragma unroll
        for (int nf = 0; nf < 4; nf++) {
            const int col = c0 + nf * 8 + 2 * tig;
            const int pi = col >> 1;
            const float bb0 = b_read[col], bb1 = b_read[col + 1];
            unsigned u0 = pack_f16(fmaxf(acc[mf][nf][0] + bb0, 0.f),
                                   fmaxf(acc[mf][nf][1] + bb1, 0.f));
            unsigned u1 = pack_f16(fmaxf(acc[mf][nf][2] + bb0, 0.f),
                                   fmaxf(acc[mf][nf][3] + bb1, 0.f));
            sS[ra * DPS + pi] = u0;       sD2[ra * DPD + pi] = u0;
            sS[(ra + 8) * DPS + pi] = u1; sD2[(ra + 8) * DPD + pi] = u1;
        }
    }
    // msg_mean -> sS kp[64,128); re-zero scratch
    {
        const int dg = rbase + arow;
        const float inv = 1.0f / fmaxf(g_cnt[dg], 1.0f);
        const float4* sp = (const float4*)(g_msg_sum + (size_t)dg * D_MSG + aq * 32);
#pragma unroll
        for (int j4 = 0; j4 < 8; j4++) {
            float4 v = sp[j4];
            const int pi = 64 + aq * 16 + 2 * j4;
            sS[arow * DPS + pi] = pack_f16(v.x * inv, v.y * inv);
            sS[arow * DPS + pi + 1] = pack_f16(v.z * inv, v.w * inv);
        }
        float4 z = {0.f, 0.f, 0.f, 0.f};
        float4* p = (float4*)(g_msg_sum + (size_t)dg * D_MSG + aq * 32);
#pragma unroll
        for (int j4 = 0; j4 < 8; j4++) p[j4] = z;
        if (aq == 0) g_cnt[dg] = 0.f;
    }

    // ---- GEMM 2: agg, K=256 (pipeline chunks 8-15) ----
    zacc(acc);
    for (int kc = 0; kc < 8; kc++) {
        const int i = 8 + kc;
        CP_WAIT1();
        __syncthreads();   // kc=0: orders epilogue/msg fill for all warps
        issueWd(i + 2);
        CP_COMMIT();
        mma_k32(sS + kc * 16, DPS, sWp[i % 3], r0, c0, gid, tig, acc);
    }
    __syncthreads();
#pragma unroll
    for (int mf = 0; mf < 2; mf++) {
        const int ra = r0 + mf * 16 + gid;
#pragma unroll
        for (int nf = 0; nf < 4; nf++) {
            const int col = c0 + nf * 8 + 2 * tig;
            const int pi = col >> 1;
            const float bb0 = b_agg[col], bb1 = b_agg[col + 1];
            sS[ra * DPS + pi] = pack_f16(fmaxf(acc[mf][nf][0] + bb0, 0.f),
                                         fmaxf(acc[mf][nf][1] + bb1, 0.f));
            sS[(ra + 8) * DPS + pi] = pack_f16(fmaxf(acc[mf][nf][2] + bb0, 0.f),
                                               fmaxf(acc[mf][nf][3] + bb1, 0.f));
        }
    }

    // ---- GEMM 3: upd, K=256 (chunks 16-23; agg from sS, dst_read from sD2) ----
    zacc(acc);
    for (int kc = 0; kc < 8; kc++) {
        const int i = 16 + kc;
        CP_WAIT1();
        __syncthreads();
        issueWd(i + 2);
        CP_COMMIT();
        if (kc < 4)
            mma_k32(sS + kc * 16, DPS, sWp[i % 3], r0, c0, gid, tig, acc);
        else
            mma_k32(sD2 + (kc - 4) * 16, DPD, sWp[i % 3], r0, c0, gid, tig, acc);
    }
    __syncthreads();
#pragma unroll
    for (int mf = 0; mf < 2; mf++) {
        const int ra = r0 + mf * 16 + gid;
#pragma unroll
        for (int nf = 0; nf < 4; nf++) {
            const int col = c0 + nf * 8 + 2 * tig;
            const int pi = col >> 1;
            const float bb0 = b_upd[col], bb1 = b_upd[col + 1];
            sS[ra * DPS + pi] = pack_f16(fmaxf(acc[mf][nf][0] + bb0, 0.f),
                                         fmaxf(acc[mf][nf][1] + bb1, 0.f));
            sS[(ra + 8) * DPS + pi] = pack_f16(fmaxf(acc[mf][nf][2] + bb0, 0.f),
                                               fmaxf(acc[mf][nf][3] + bb1, 0.f));
        }
    }

    // ---- GEMM 4: write = tanh(upd @ W_write + b), K=128 (chunks 24-27) ----
    zacc(acc);
    for (int kc = 0; kc < 4; kc++) {
        const int i = 24 + kc;
        CP_WAIT1();
        __syncthreads();
        issueWd(i + 2);    // no-op for i+2 >= 28
        CP_COMMIT();       // empty groups keep the wait invariant exact
        mma_k32(sS + kc * 16, DPS, sWp[i % 3], r0, c0, gid, tig, acc);
    }
#pragma unroll
    for (int mf = 0; mf < 2; mf++) {
        const int ra = r0 + mf * 16 + gid;
        const int n0 = s_nid[ra], n1 = s_nid[ra + 8];
#pragma unroll
        for (int nf = 0; nf < 4; nf++) {
            const int col = c0 + nf * 8 + 2 * tig;
            const float bb0 = b_write[col], bb1 = b_write[col + 1];
            float2 o0, o1;
            o0.x = tanhf(acc[mf][nf][0] + bb0);
            o0.y = tanhf(acc[mf][nf][1] + bb1);
            o1.x = tanhf(acc[mf][nf][2] + bb0);
            o1.y = tanhf(acc[mf][nf][3] + bb1);
            *(float2*)(out + (size_t)n0 * D_MEM + col) = o0;
            *(float2*)(out + (size_t)n1 * D_MEM + col) = o1;
        }
    }
}

// ---------------- launch ------------------------------------------------------
extern "C" void kernel_launch(void* const* d_in, const int* in_sizes, int n_in,
                              void* d_out, int out_size) {
    const float* node_memory   = (const float*)d_in[0];
    const float* node_features = (const float*)d_in[1];
    const float* edge_features = (const float*)d_in[2];
    const float* time_encoding = (const float*)d_in[3];
    const void*  node_ids      = d_in[4];
    const void*  source_ids    = d_in[5];
    const void*  edge_ids      = d_in[6];
    const void*  dest_seg      = d_in[7];
    const float* W_read  = (const float*)d_in[8];
    const float* b_read  = (const float*)d_in[9];
    const float* W_msg   = (const float*)d_in[10];
    const float* b_msg   = (const float*)d_in[11];
    const float* W_agg   = (const float*)d_in[12];
    const float* b_agg   = (const float*)d_in[13];
    const float* W_upd   = (const float*)d_in[14];
    const float* b_upd   = (const float*)d_in[15];
    const float* W_write = (const float*)d_in[16];
    const float* b_write = (const float*)d_in[17];
    float* out = (float*)d_out;

    cudaFuncSetAttribute(edge_kernel, cudaFuncAttributeMaxDynamicSharedMemorySize, EDGE_SMEM);
    cudaFuncSetAttribute(dest_kernel, cudaFuncAttributeMaxDynamicSharedMemorySize, DEST_SMEM);

    prep_kernel<<<280, 256>>>(W_read, W_msg, W_agg, W_upd, W_write);

    edge_kernel<<<N_EDGE / 64, 256, EDGE_SMEM>>>(
        node_memory, node_features, edge_features, time_encoding, node_ids,
        source_ids, edge_ids, dest_seg, b_read, b_msg, out);

    dest_kernel<<<N_DEST / 64, 256, DEST_SMEM>>>(
        node_memory, node_features, node_ids,
        b_read, b_agg, b_upd, b_write, out);
}

// round 16
// speedup vs baseline: 1.8651x; 1.0707x over previous
#include <cuda_runtime.h>
#include <cuda_fp16.h>
#include <math.h>

#define N_NODES 200000
#define N_DEST  8192
#define N_EDGE  262144
#define D_MEM   128
#define D_FEAT  128
#define D_EDGE  64
#define D_TIME  32
#define D_MSG   128

// ---------------- scratch (device globals: allocation-free) ------------------
__device__ float g_msg_sum[N_DEST * D_MSG];   // zero-init; dest_kernel re-zeroes
__device__ float g_cnt[N_DEST];
// pre-packed fp16x2 W chunks [chunk][kp][128]:
// 0-7 W_read, 8-14 W_msg, 15-22 W_agg, 23-30 W_upd, 31-34 W_write
__device__ unsigned g_Wf[35 * 2048];
// packed fp16x2 node readout table: [node][kp 0..63]  (51.2 MB)
__device__ unsigned g_noderead[(size_t)N_NODES * 64];

__device__ __forceinline__ int idx_at(const void* p, long long i, int is64) {
    return is64 ? (int)((const long long*)p)[i] : ((const int*)p)[i];
}

// ---------------- fp16 pack / mma ----------------------------------------------
__device__ __forceinline__ unsigned pack_f16(float x0, float x1) {
    unsigned r;
    asm("cvt.rn.f16x2.f32 %0, %1, %2;" : "=r"(r) : "f"(x1), "f"(x0));
    return r;
}

__device__ __forceinline__ void mma_f16(float* c, const unsigned* a, const unsigned* b) {
    asm volatile(
        "mma.sync.aligned.m16n8k16.row.col.f32.f16.f16.f32 "
        "{%0,%1,%2,%3},{%4,%5,%6,%7},{%8,%9},{%0,%1,%2,%3};"
        : "+f"(c[0]), "+f"(c[1]), "+f"(c[2]), "+f"(c[3])
        : "r"(a[0]), "r"(a[1]), "r"(a[2]), "r"(a[3]), "r"(b[0]), "r"(b[1]));
}

// ---------------- cp.async helpers --------------------------------------------
__device__ __forceinline__ void cp16(unsigned dst_smem, const void* src) {
    asm volatile("cp.async.cg.shared.global [%0], [%1], 16;"
                 :: "r"(dst_smem), "l"(src));
}
#define CP_COMMIT() asm volatile("cp.async.commit_group;")
#define CP_WAIT1()  asm volatile("cp.async.wait_group 1;" ::: "memory")

// ---------------- prep: pre-pack ALL weights into fp16x2 ----------------------
__global__ void prep_kernel(const float* __restrict__ W_read,
                            const float* __restrict__ W_msg,
                            const float* __restrict__ W_agg,
                            const float* __restrict__ W_upd,
                            const float* __restrict__ W_write) {
    const int idx = blockIdx.x * blockDim.x + threadIdx.x;
    if (idx >= 35 * 2048) return;
    const int chunk = idx >> 11;
    const int kp = (idx >> 7) & 15;
    const int c = idx & 127;
    const float* W;
    int cl;
    if (chunk < 8)       { W = W_read;  cl = chunk; }
    else if (chunk < 15) { W = W_msg;   cl = chunk - 8; }
    else if (chunk < 23) { W = W_agg;   cl = chunk - 15; }
    else if (chunk < 31) { W = W_upd;   cl = chunk - 23; }
    else                 { W = W_write; cl = chunk - 31; }
    const int row = cl * 32 + 2 * kp;
    g_Wf[idx] = pack_f16(W[row * 128 + c], W[(row + 1) * 128 + c]);
}

// ---------------- shared mma chunks --------------------------------------------
#define PW 136
#define PFA 40   // fp32 staging stride (conflict-free LDS.64)

// fp32-acc chunk over packed fp16 A
__device__ __forceinline__ void mma_k32(const unsigned* __restrict__ Ah, int strideA,
                                        const unsigned* __restrict__ Wh,
                                        int r0, int c0, int gid, int tig,
                                        float acc[2][4][4]) {
#pragma unroll
    for (int half = 0; half < 2; half++) {
        const int kb = half * 8;
        unsigned ah[2][4];
#pragma unroll
        for (int mf = 0; mf < 2; mf++) {
            const int ra = r0 + mf * 16 + gid;
            ah[mf][0] = Ah[ra * strideA + kb + tig];
            ah[mf][1] = Ah[(ra + 8) * strideA + kb + tig];
            ah[mf][2] = Ah[ra * strideA + kb + tig + 4];
            ah[mf][3] = Ah[(ra + 8) * strideA + kb + tig + 4];
        }
#pragma unroll
        for (int nf = 0; nf < 4; nf++) {
            const int col = c0 + nf * 8 + gid;
            unsigned bh[2];
            bh[0] = Wh[(kb + tig) * PW + col];
            bh[1] = Wh[(kb + tig + 4) * PW + col];
#pragma unroll
            for (int mf = 0; mf < 2; mf++) mma_f16(acc[mf][nf], ah[mf], bh);
        }
    }
}

// fp32-acc chunk over fp32 staging A (fragments cvt'd on load)
__device__ __forceinline__ void mma_k32_f32(const float* __restrict__ A,
                                            const unsigned* __restrict__ Wh,
                                            int r0, int c0, int gid, int tig,
                                            float acc[2][4][4]) {
#pragma unroll
    for (int half = 0; half < 2; half++) {
        const int kf = half * 16 + 2 * tig;
        unsigned ah[2][4];
#pragma unroll
        for (int mf = 0; mf < 2; mf++) {
            const int ra = r0 + mf * 16 + gid;
            const float2 v0 = *(const float2*)(A + ra * PFA + kf);
            const float2 v1 = *(const float2*)(A + (ra + 8) * PFA + kf);
            const float2 v2 = *(const float2*)(A + ra * PFA + kf + 8);
            const float2 v3 = *(const float2*)(A + (ra + 8) * PFA + kf + 8);
            ah[mf][0] = pack_f16(v0.x, v0.y);
            ah[mf][1] = pack_f16(v1.x, v1.y);
            ah[mf][2] = pack_f16(v2.x, v2.y);
            ah[mf][3] = pack_f16(v3.x, v3.y);
        }
        const int kb = half * 8;
#pragma unroll
        for (int nf = 0; nf < 4; nf++) {
            const int col = c0 + nf * 8 + gid;
            unsigned bh[2];
            bh[0] = Wh[(kb + tig) * PW + col];
            bh[1] = Wh[(kb + tig + 4) * PW + col];
#pragma unroll
            for (int mf = 0; mf < 2; mf++) mma_f16(acc[mf][nf], ah[mf], bh);
        }
    }
}

__device__ __forceinline__ void zacc(float acc[2][4][4]) {
#pragma unroll
    for (int m = 0; m < 2; m++)
#pragma unroll
        for (int n = 0; n < 4; n++)
#pragma unroll
            for (int c = 0; c < 4; c++) acc[m][n][c] = 0.f;
}

// ---------------- node_read kernel: dense readout for ALL nodes ---------------
// R = relu([node_memory|node_features] @ W_read + b_read) -> g_noderead (fp16x2)
// Also folds the node_memory -> out copy (staging already holds those bytes).
#define NR_FA0 0
#define NR_FA1 2560
#define NR_FA2 5120
#define NR_W0  7680
#define NR_W1  9856
#define NR_W2  12032
#define NR_U32 14208
#define NR_SMEM (NR_U32 * 4)   // 56832 B -> 2 CTAs/SM

__global__ __launch_bounds__(256, 2) void node_read_kernel(
    const float* __restrict__ node_memory, const float* __restrict__ node_features,
    const float* __restrict__ b_read, float* __restrict__ out) {
    extern __shared__ unsigned su[];
    const float* fpA[3] = {(const float*)(su + NR_FA0), (const float*)(su + NR_FA1),
                           (const float*)(su + NR_FA2)};
    unsigned* const sWp[3] = {su + NR_W0, su + NR_W1, su + NR_W2};

    const int tid = threadIdx.x;
    const int lane = tid & 31;
    const int warp = tid >> 5;
    const int gid = lane >> 2;
    const int tig = lane & 3;
    const int r0 = (warp >> 2) * 32;
    const int c0 = (warp & 3) * 32;
    const int rbase = blockIdx.x * 64;

    const int arow = tid >> 2;
    const int aq = tid & 3;
    const int wkp = tid >> 4;
    const int wc8 = (tid & 15) * 8;

    const unsigned smb = (unsigned)__cvta_generic_to_shared(su);
    const unsigned faB[3] = {smb + NR_FA0 * 4, smb + NR_FA1 * 4, smb + NR_FA2 * 4};
    const unsigned whB[3] = {smb + NR_W0 * 4, smb + NR_W1 * 4, smb + NR_W2 * 4};

    auto issueA = [&](int kc) {
        const size_t row = (size_t)(rbase + arow);
        const float* base = (kc < 4)
            ? node_memory + row * D_MEM + kc * 32
            : node_features + row * D_FEAT + (kc - 4) * 32;
        const unsigned d = faB[kc % 3] + (arow * PFA + aq * 8) * 4;
        cp16(d, base + aq * 8);
        cp16(d + 16, base + aq * 8 + 4);
    };
    auto issueW = [&](int kc) {
        if (kc >= 8) return;
        const unsigned* src = g_Wf + kc * 2048 + wkp * 128 + wc8;
        const unsigned d = whB[kc % 3] + (wkp * PW + wc8) * 4;
        cp16(d, src);
        cp16(d + 16, src + 4);
    };

    issueA(0); issueW(0); CP_COMMIT();
    issueA(1); issueW(1); CP_COMMIT();

    float acc[2][4][4];
    zacc(acc);

    for (int kc = 0; kc < 8; kc++) {
        CP_WAIT1();
        __syncthreads();
        if (kc < 6) issueA(kc + 2);
        issueW(kc + 2);
        CP_COMMIT();   // possibly-empty group keeps the wait invariant exact
        // fold the node_memory -> out copy (chunks 0-3 hold node_memory bytes)
        if (kc < 4) {
            const float* f = fpA[kc % 3] + arow * PFA + aq * 8;
            float4 v0 = *(const float4*)f;
            float4 v1 = *(const float4*)(f + 4);
            float* o = out + (size_t)(rbase + arow) * D_MEM + kc * 32 + aq * 8;
            *(float4*)o = v0;
            *(float4*)(o + 4) = v1;
        }
        mma_k32_f32(fpA[kc % 3], sWp[kc % 3], r0, c0, gid, tig, acc);
    }

    // epilogue: bias+relu, pack fp16x2 -> g_noderead
#pragma unroll
    for (int mf = 0; mf < 2; mf++) {
        const int ra = r0 + mf * 16 + gid;
#pragma unroll
        for (int nf = 0; nf < 4; nf++) {
            const int col = c0 + nf * 8 + 2 * tig;
            const int pi = col >> 1;
            const float bb0 = b_read[col], bb1 = b_read[col + 1];
            g_noderead[(size_t)(rbase + ra) * 64 + pi] =
                pack_f16(fmaxf(acc[mf][nf][0] + bb0, 0.f),
                         fmaxf(acc[mf][nf][1] + bb1, 0.f));
            g_noderead[(size_t)(rbase + ra + 8) * 64 + pi] =
                pack_f16(fmaxf(acc[mf][nf][2] + bb0, 0.f),
                         fmaxf(acc[mf][nf][3] + bb1, 0.f));
        }
    }
}

// ---------------- edge kernel: msg GEMM only (src_read gathered) --------------
#define PS 116
#define STRIDE_M 132

#define E2_ST 0        // stage: 64*116 = 7424
#define E2_W0 7424
#define E2_W1 9600
#define E2_W2 11776
#define E2_U32 13952
#define EDGE_SMEM (E2_U32 * 4)   // 55808 B
// msg fp32 buffer (64*132 = 8448 u32) aliases [0, 8448) after the mma loop

__device__ __forceinline__ void flush_seg(int d, int tx, const float* r, float rl) {
    float* p = g_msg_sum + (size_t)d * D_MSG + tx * 4;
    atomicAdd(p + 0, r[0]);
    atomicAdd(p + 1, r[1]);
    atomicAdd(p + 2, r[2]);
    atomicAdd(p + 3, r[3]);
    if (tx == 0) atomicAdd(&g_cnt[d], rl);
}

__global__ __launch_bounds__(256, 2) void edge_kernel(
    const float* __restrict__ edge_features, const float* __restrict__ time_encoding,
    const void* __restrict__ node_ids,
    const void* __restrict__ source_ids, const void* __restrict__ edge_ids,
    const void* __restrict__ dest_seg,
    const float* __restrict__ b_msg) {
    extern __shared__ unsigned su[];
    unsigned* sSh = su + E2_ST;
    unsigned* const sWp[3] = {su + E2_W0, su + E2_W1, su + E2_W2};
    __shared__ int s_src[64], s_eid[64], s_dst[64];

    const int tid = threadIdx.x;
    const int lane = tid & 31;
    const int warp = tid >> 5;
    const int gid = lane >> 2;
    const int tig = lane & 3;
    const int r0 = (warp >> 2) * 32;
    const int c0 = (warp & 3) * 32;
    const long long ebase = (long long)blockIdx.x * 64;

    const unsigned* nwid = (const unsigned*)node_ids;
    const int is64 = (nwid[1] == 0u && nwid[3] == 0u);

    if (tid < 64) {
        s_src[tid] = idx_at(source_ids, ebase + tid, is64);
        s_eid[tid] = idx_at(edge_ids, ebase + tid, is64);
        s_dst[tid] = idx_at(dest_seg, ebase + tid, is64);
    }
    __syncthreads();

    const int arow = tid >> 2;
    const int aq = tid & 3;
    const int wkp = tid >> 4;
    const int wc8 = (tid & 15) * 8;

    const unsigned smb = (unsigned)__cvta_generic_to_shared(su);
    const unsigned stB = smb + E2_ST * 4;
    const unsigned whB[3] = {smb + E2_W0 * 4, smb + E2_W1 * 4, smb + E2_W2 * 4};

    auto issueW = [&](int i) {   // msg chunk i (0..6) -> g_Wf chunk 8+i
        if (i >= 7) return;
        const unsigned* src = g_Wf + (8 + i) * 2048 + wkp * 128 + wc8;
        const unsigned d = whB[i % 3] + (wkp * PW + wc8) * 4;
        cp16(d, src);
        cp16(d + 16, src + 4);
    };

    // prologue group 0: src_read row gather (pre-packed fp16!) + W chunk 0
    {
        const unsigned* src = g_noderead + (size_t)s_src[arow] * 64 + aq * 16;
        const unsigned d = stB + (arow * PS + aq * 16) * 4;
#pragma unroll
        for (int j = 0; j < 4; j++) cp16(d + j * 16, src + j * 4);
    }
    issueW(0);
    CP_COMMIT();
    issueW(1);
    CP_COMMIT();

    // prefill stage kpairs [64,112): edge feats, time (overlaps prologue loads)
    {
        const float4* ef = (const float4*)(edge_features + (size_t)s_eid[arow] * D_EDGE);
#pragma unroll
        for (int j = 0; j < 4; j++) {
            float4 v = ef[aq * 4 + j];
            const int pi = 64 + aq * 8 + 2 * j;
            sSh[arow * PS + pi] = pack_f16(v.x, v.y);
            sSh[arow * PS + pi + 1] = pack_f16(v.z, v.w);
        }
        const float4* tf = (const float4*)(time_encoding + (ebase + arow) * D_TIME);
#pragma unroll
        for (int j = 0; j < 2; j++) {
            float4 v = tf[aq * 2 + j];
            const int pi = 96 + aq * 4 + 2 * j;
            sSh[arow * PS + pi] = pack_f16(v.x, v.y);
            sSh[arow * PS + pi + 1] = pack_f16(v.z, v.w);
        }
    }

    float acc[2][4][4];
    zacc(acc);

    // ---- msgs = relu([src_read|ef|time] @ W_msg + b), K=224, depth-2 pipe ----
    for (int kc = 0; kc < 7; kc++) {
        CP_WAIT1();          // group kc landed (gather rode in group 0)
        __syncthreads();
        issueW(kc + 2);
        CP_COMMIT();         // possibly-empty group keeps the invariant
        mma_k32(sSh + kc * 16, PS, sWp[kc % 3], r0, c0, gid, tig, acc);
    }
    __syncthreads();   // all warps done reading stage/W before msg overwrite

    // ---- epilogue: msgs -> fp32 msg buffer (aliases stage + W0) ----
    float* msg = (float*)su;
#pragma unroll
    for (int mf = 0; mf < 2; mf++) {
        const int ra = r0 + mf * 16 + gid;
#pragma unroll
        for (int nf = 0; nf < 4; nf++) {
            const int col = c0 + nf * 8 + 2 * tig;
            const float b0 = b_msg[col], b1 = b_msg[col + 1];
            msg[ra * STRIDE_M + col]           = fmaxf(acc[mf][nf][0] + b0, 0.f);
            msg[ra * STRIDE_M + col + 1]       = fmaxf(acc[mf][nf][1] + b1, 0.f);
            msg[(ra + 8) * STRIDE_M + col]     = fmaxf(acc[mf][nf][2] + b0, 0.f);
            msg[(ra + 8) * STRIDE_M + col + 1] = fmaxf(acc[mf][nf][3] + b1, 0.f);
        }
    }
    __syncthreads();

    // ---- run-coalesced segment-sum atomics (dest_seg globally sorted) ----
    {
        const int tx = lane;
        const int e0 = warp * 8;
        int curd = s_dst[e0];
        float r[4] = {0.f, 0.f, 0.f, 0.f};
        float rl = 0.f;
#pragma unroll
        for (int i = 0; i < 8; i++) {
            const int e = e0 + i;
            const int d = s_dst[e];
            const float4 v = *(const float4*)(msg + e * STRIDE_M + tx * 4);
            if (d != curd) {
                flush_seg(curd, tx, r, rl);
                curd = d;
                r[0] = r[1] = r[2] = r[3] = 0.f;
                rl = 0.f;
            }
            r[0] += v.x; r[1] += v.y; r[2] += v.z; r[3] += v.w;
            rl += 1.f;
        }
        flush_seg(curd, tx, r, rl);
    }
}

// ---------------- dest kernel: dst_read gathered; 20-chunk pipeline -----------
#define DPS 132
#define DPD 68

#define D2_W0 0
#define D2_W1 2176
#define D2_W2 4352
#define D2_S  6528     // sS: 64*132 = 8448
#define D2_D  14976    // sD2: 64*68 = 4352
#define DEST_U32 19328
#define DEST_SMEM (DEST_U32 * 4)   // 77312 B -> 1 CTA/SM (1 wave anyway)

__global__ __launch_bounds__(256, 1) void dest_kernel(
    const void* __restrict__ node_ids,
    const float* __restrict__ b_agg, const float* __restrict__ b_upd,
    const float* __restrict__ b_write, float* __restrict__ out) {
    extern __shared__ unsigned su[];
    unsigned* const sWp[3] = {su + D2_W0, su + D2_W1, su + D2_W2};
    unsigned* sS = su + D2_S;
    unsigned* sD2 = su + D2_D;
    __shared__ int s_nid[64];

    const int tid = threadIdx.x;
    const int lane = tid & 31;
    const int warp = tid >> 5;
    const int gid = lane >> 2;
    const int tig = lane & 3;
    const int r0 = (warp >> 2) * 32;
    const int c0 = (warp & 3) * 32;
    const int rbase = blockIdx.x * 64;

    const unsigned* nwid = (const unsigned*)node_ids;
    const int is64 = (nwid[1] == 0u && nwid[3] == 0u);

    if (tid < 64) s_nid[tid] = idx_at(node_ids, rbase + tid, is64);
    __syncthreads();

    const int arow = tid >> 2;
    const int aq = tid & 3;
    const int wkp = tid >> 4;
    const int wc8 = (tid & 15) * 8;

    const unsigned smb = (unsigned)__cvta_generic_to_shared(su);
    const unsigned sSB = smb + D2_S * 4;
    const unsigned whB[3] = {smb + D2_W0 * 4, smb + D2_W1 * 4, smb + D2_W2 * 4};

    auto issueW = [&](int i) {   // seq chunk i (0..19) -> g_Wf chunk 15+i
        if (i >= 20) return;
        const unsigned* src = g_Wf + (15 + i) * 2048 + wkp * 128 + wc8;
        const unsigned d = whB[i % 3] + (wkp * PW + wc8) * 4;
        cp16(d, src);
        cp16(d + 16, src + 4);
    };

    // prologue group 0: dst_read row gather (pre-packed fp16) + W chunk 0
    {
        const unsigned* src = g_noderead + (size_t)s_nid[arow] * 64 + aq * 16;
        const unsigned d = sSB + (arow * DPS + aq * 16) * 4;
#pragma unroll
        for (int j = 0; j < 4; j++) cp16(d + j * 16, src + j * 4);
    }
    issueW(0);
    CP_COMMIT();
    issueW(1);
    CP_COMMIT();

    CP_WAIT1();        // group 0 (gather + W0) landed
    __syncthreads();

    // copy dst_read sS -> sD2 (needed by upd GEMM after agg overwrites sS)
    {
#pragma unroll
        for (int j = 0; j < 4; j++) {
            const int off = (tid * 4 + j) * 4;      // u32 offset in 64x64 region
            const int row = off >> 6;
            const int pi = off & 63;
            *(uint4*)(sD2 + row * DPD + pi) = *(const uint4*)(sS + row * DPS + pi);
        }
    }
    // msg_mean -> sS kp[64,128); re-zero scratch
    {
        const int dg = rbase + arow;
        const float inv = 1.0f / fmaxf(g_cnt[dg], 1.0f);
        const float4* sp = (const float4*)(g_msg_sum + (size_t)dg * D_MSG + aq * 32);
#pragma unroll
        for (int j4 = 0; j4 < 8; j4++) {
            float4 v = sp[j4];
            const int pi = 64 + aq * 16 + 2 * j4;
            sS[arow * DPS + pi] = pack_f16(v.x * inv, v.y * inv);
            sS[arow * DPS + pi + 1] = pack_f16(v.z * inv, v.w * inv);
        }
        float4 z = {0.f, 0.f, 0.f, 0.f};
        float4* p = (float4*)(g_msg_sum + (size_t)dg * D_MSG + aq * 32);
#pragma unroll
        for (int j4 = 0; j4 < 8; j4++) p[j4] = z;
        if (aq == 0) g_cnt[dg] = 0.f;
    }
    __syncthreads();

    float acc[2][4][4];

    // ---- GEMM agg: K=256 (seq chunks 0-7) ----
    zacc(acc);
    for (int kc = 0; kc < 8; kc++) {
        CP_WAIT1();
        __syncthreads();
        issueW(kc + 2);
        CP_COMMIT();
        mma_k32(sS + kc * 16, DPS, sWp[kc % 3], r0, c0, gid, tig, acc);
    }
    __syncthreads();
#pragma unroll
    for (int mf = 0; mf < 2; mf++) {
        const int ra = r0 + mf * 16 + gid;
#pragma unroll
        for (int nf = 0; nf < 4; nf++) {
            const int col = c0 + nf * 8 + 2 * tig;
            const int pi = col >> 1;
            const float bb0 = b_agg[col], bb1 = b_agg[col + 1];
            sS[ra * DPS + pi] = pack_f16(fmaxf(acc[mf][nf][0] + bb0, 0.f),
                                         fmaxf(acc[mf][nf][1] + bb1, 0.f));
            sS[(ra + 8) * DPS + pi] = pack_f16(fmaxf(acc[mf][nf][2] + bb0, 0.f),
                                               fmaxf(acc[mf][nf][3] + bb1, 0.f));
        }
    }

    // ---- GEMM upd: K=256 (seq chunks 8-15; agg from sS, dst_read from sD2) ----
    zacc(acc);
    for (int kc = 0; kc < 8; kc++) {
        const int i = 8 + kc;
        CP_WAIT1();
        __syncthreads();   // kc=0: orders agg epilogue for all warps
        issueW(i + 2);
        CP_COMMIT();
        if (kc < 4)
            mma_k32(sS + kc * 16, DPS, sWp[i % 3], r0, c0, gid, tig, acc);
        else
            mma_k32(sD2 + (kc - 4) * 16, DPD, sWp[i % 3], r0, c0, gid, tig, acc);
    }
    __syncthreads();
#pragma unroll
    for (int mf = 0; mf < 2; mf++) {
        const int ra = r0 + mf * 16 + gid;
#pragma unroll
        for (int nf = 0; nf < 4; nf++) {
            const int col = c0 + nf * 8 + 2 * tig;
            const int pi = col >> 1;
            const float bb0 = b_upd[col], bb1 = b_upd[col + 1];
            sS[ra * DPS + pi] = pack_f16(fmaxf(acc[mf][nf][0] + bb0, 0.f),
                                         fmaxf(acc[mf][nf][1] + bb1, 0.f));
            sS[(ra + 8) * DPS + pi] = pack_f16(fmaxf(acc[mf][nf][2] + bb0, 0.f),
                                               fmaxf(acc[mf][nf][3] + bb1, 0.f));
        }
    }

    // ---- GEMM write: K=128 (seq chunks 16-19); tanh + scatter ----
    zacc(acc);
    for (int kc = 0; kc < 4; kc++) {
        const int i = 16 + kc;
        CP_WAIT1();
        __syncthreads();
        issueW(i + 2);     // no-op for i+2 >= 20
        CP_COMMIT();
        mma_k32(sS + kc * 16, DPS, sWp[i % 3], r0, c0, gid, tig, acc);
    }
#pragma unroll
    for (int mf = 0; mf < 2; mf++) {
        const int ra = r0 + mf * 16 + gid;
        const int n0 = s_nid[ra], n1 = s_nid[ra + 8];
#pragma unroll
        for (int nf = 0; nf < 4; nf++) {
            const int col = c0 + nf * 8 + 2 * tig;
            const float bb0 = b_write[col], bb1 = b_write[col + 1];
            float2 o0, o1;
            o0.x = tanhf(acc[mf][nf][0] + bb0);
            o0.y = tanhf(acc[mf][nf][1] + bb1);
            o1.x = tanhf(acc[mf][nf][2] + bb0);
            o1.y = tanhf(acc[mf][nf][3] + bb1);
            *(float2*)(out + (size_t)n0 * D_MEM + col) = o0;
            *(float2*)(out + (size_t)n1 * D_MEM + col) = o1;
        }
    }
}

// ---------------- launch ------------------------------------------------------
extern "C" void kernel_launch(void* const* d_in, const int* in_sizes, int n_in,
                              void* d_out, int out_size) {
    const float* node_memory   = (const float*)d_in[0];
    const float* node_features = (const float*)d_in[1];
    const float* edge_features = (const float*)d_in[2];
    const float* time_encoding = (const float*)d_in[3];
    const void*  node_ids      = d_in[4];
    const void*  source_ids    = d_in[5];
    const void*  edge_ids      = d_in[6];
    const void*  dest_seg      = d_in[7];
    const float* W_read  = (const float*)d_in[8];
    const float* b_read  = (const float*)d_in[9];
    const float* W_msg   = (const float*)d_in[10];
    const float* b_msg   = (const float*)d_in[11];
    const float* W_agg   = (const float*)d_in[12];
    const float* b_agg   = (const float*)d_in[13];
    const float* W_upd   = (const float*)d_in[14];
    const float* b_upd   = (const float*)d_in[15];
    const float* W_write = (const float*)d_in[16];
    const float* b_write = (const float*)d_in[17];
    float* out = (float*)d_out;

    cudaFuncSetAttribute(node_read_kernel, cudaFuncAttributeMaxDynamicSharedMemorySize, NR_SMEM);
    cudaFuncSetAttribute(edge_kernel, cudaFuncAttributeMaxDynamicSharedMemorySize, EDGE_SMEM);
    cudaFuncSetAttribute(dest_kernel, cudaFuncAttributeMaxDynamicSharedMemorySize, DEST_SMEM);

    prep_kernel<<<280, 256>>>(W_read, W_msg, W_agg, W_upd, W_write);

    node_read_kernel<<<N_NODES / 64, 256, NR_SMEM>>>(
        node_memory, node_features, b_read, out);

    edge_kernel<<<N_EDGE / 64, 256, EDGE_SMEM>>>(
        edge_features, time_encoding, node_ids,
        source_ids, edge_ids, dest_seg, b_msg);

    dest_kernel<<<N_DEST / 64, 256, DEST_SMEM>>>(
        node_ids, b_agg, b_upd, b_write, out);
}

// round 17
// speedup vs baseline: 1.9060x; 1.0219x over previous
#include <cuda_runtime.h>
#include <cuda_fp16.h>
#include <math.h>

#define N_NODES 200000
#define N_DEST  8192
#define N_EDGE  262144
#define D_MEM   128
#define D_FEAT  128
#define D_EDGE  64
#define D_TIME  32
#define D_MSG   128

// ---------------- scratch (device globals: allocation-free) ------------------
__device__ float g_msg_sum[N_DEST * D_MSG];   // zero-init; dest_kernel re-zeroes
__device__ float g_cnt[N_DEST];
// pre-packed fp16x2 W chunks [chunk][kp][128]:
// 0-7 W_read, 8-14 W_msg, 15-22 W_agg, 23-30 W_upd, 31-34 W_write
__device__ unsigned g_Wf[35 * 2048];
// packed fp16x2 node readout table: [node][kp 0..63]  (51.2 MB)
__device__ unsigned g_noderead[(size_t)N_NODES * 64];

__device__ __forceinline__ int idx_at(const void* p, long long i, int is64) {
    return is64 ? (int)((const long long*)p)[i] : ((const int*)p)[i];
}

// ---------------- fp16 pack / mma ----------------------------------------------
__device__ __forceinline__ unsigned pack_f16(float x0, float x1) {
    unsigned r;
    asm("cvt.rn.f16x2.f32 %0, %1, %2;" : "=r"(r) : "f"(x1), "f"(x0));
    return r;
}

__device__ __forceinline__ void mma_f16(float* c, const unsigned* a, const unsigned* b) {
    asm volatile(
        "mma.sync.aligned.m16n8k16.row.col.f32.f16.f16.f32 "
        "{%0,%1,%2,%3},{%4,%5,%6,%7},{%8,%9},{%0,%1,%2,%3};"
        : "+f"(c[0]), "+f"(c[1]), "+f"(c[2]), "+f"(c[3])
        : "r"(a[0]), "r"(a[1]), "r"(a[2]), "r"(a[3]), "r"(b[0]), "r"(b[1]));
}

// ---------------- cp.async helpers --------------------------------------------
__device__ __forceinline__ void cp16(unsigned dst_smem, const void* src) {
    asm volatile("cp.async.cg.shared.global [%0], [%1], 16;"
                 :: "r"(dst_smem), "l"(src));
}
#define CP_COMMIT() asm volatile("cp.async.commit_group;")
#define CP_WAIT1()  asm volatile("cp.async.wait_group 1;" ::: "memory")

// ---------------- prep: pre-pack ALL weights into fp16x2 ----------------------
__global__ void prep_kernel(const float* __restrict__ W_read,
                            const float* __restrict__ W_msg,
                            const float* __restrict__ W_agg,
                            const float* __restrict__ W_upd,
                            const float* __restrict__ W_write) {
    const int idx = blockIdx.x * blockDim.x + threadIdx.x;
    if (idx >= 35 * 2048) return;
    const int chunk = idx >> 11;
    const int kp = (idx >> 7) & 15;
    const int c = idx & 127;
    const float* W;
    int cl;
    if (chunk < 8)       { W = W_read;  cl = chunk; }
    else if (chunk < 15) { W = W_msg;   cl = chunk - 8; }
    else if (chunk < 23) { W = W_agg;   cl = chunk - 15; }
    else if (chunk < 31) { W = W_upd;   cl = chunk - 23; }
    else                 { W = W_write; cl = chunk - 31; }
    const int row = cl * 32 + 2 * kp;
    g_Wf[idx] = pack_f16(W[row * 128 + c], W[(row + 1) * 128 + c]);
}

// ---------------- shared mma chunks --------------------------------------------
#define PW 136
#define PFA 40   // fp32 staging stride (conflict-free LDS.64)

// fp32-acc chunk over packed fp16 A, warp tile 32x32 (4 col-fragments)
__device__ __forceinline__ void mma_k32(const unsigned* __restrict__ Ah, int strideA,
                                        const unsigned* __restrict__ Wh,
                                        int r0, int c0, int gid, int tig,
                                        float acc[2][4][4]) {
#pragma unroll
    for (int half = 0; half < 2; half++) {
        const int kb = half * 8;
        unsigned ah[2][4];
#pragma unroll
        for (int mf = 0; mf < 2; mf++) {
            const int ra = r0 + mf * 16 + gid;
            ah[mf][0] = Ah[ra * strideA + kb + tig];
            ah[mf][1] = Ah[(ra + 8) * strideA + kb + tig];
            ah[mf][2] = Ah[ra * strideA + kb + tig + 4];
            ah[mf][3] = Ah[(ra + 8) * strideA + kb + tig + 4];
        }
#pragma unroll
        for (int nf = 0; nf < 4; nf++) {
            const int col = c0 + nf * 8 + gid;
            unsigned bh[2];
            bh[0] = Wh[(kb + tig) * PW + col];
            bh[1] = Wh[(kb + tig + 4) * PW + col];
#pragma unroll
            for (int mf = 0; mf < 2; mf++) mma_f16(acc[mf][nf], ah[mf], bh);
        }
    }
}

// fp32-acc chunk over packed fp16 A, warp tile 32x16 (2 col-fragments, dest)
__device__ __forceinline__ void mma_k32_n16(const unsigned* __restrict__ Ah, int strideA,
                                            const unsigned* __restrict__ Wh,
                                            int c0, int gid, int tig,
                                            float acc[2][2][4]) {
#pragma unroll
    for (int half = 0; half < 2; half++) {
        const int kb = half * 8;
        unsigned ah[2][4];
#pragma unroll
        for (int mf = 0; mf < 2; mf++) {
            const int ra = mf * 16 + gid;
            ah[mf][0] = Ah[ra * strideA + kb + tig];
            ah[mf][1] = Ah[(ra + 8) * strideA + kb + tig];
            ah[mf][2] = Ah[ra * strideA + kb + tig + 4];
            ah[mf][3] = Ah[(ra + 8) * strideA + kb + tig + 4];
        }
#pragma unroll
        for (int nf = 0; nf < 2; nf++) {
            const int col = c0 + nf * 8 + gid;
            unsigned bh[2];
            bh[0] = Wh[(kb + tig) * PW + col];
            bh[1] = Wh[(kb + tig + 4) * PW + col];
#pragma unroll
            for (int mf = 0; mf < 2; mf++) mma_f16(acc[mf][nf], ah[mf], bh);
        }
    }
}

// fp32-acc chunk over fp32 staging A (fragments cvt'd on load)
__device__ __forceinline__ void mma_k32_f32(const float* __restrict__ A,
                                            const unsigned* __restrict__ Wh,
                                            int r0, int c0, int gid, int tig,
                                            float acc[2][4][4]) {
#pragma unroll
    for (int half = 0; half < 2; half++) {
        const int kf = half * 16 + 2 * tig;
        unsigned ah[2][4];
#pragma unroll
        for (int mf = 0; mf < 2; mf++) {
            const int ra = r0 + mf * 16 + gid;
            const float2 v0 = *(const float2*)(A + ra * PFA + kf);
            const float2 v1 = *(const float2*)(A + (ra + 8) * PFA + kf);
            const float2 v2 = *(const float2*)(A + ra * PFA + kf + 8);
            const float2 v3 = *(const float2*)(A + (ra + 8) * PFA + kf + 8);
            ah[mf][0] = pack_f16(v0.x, v0.y);
            ah[mf][1] = pack_f16(v1.x, v1.y);
            ah[mf][2] = pack_f16(v2.x, v2.y);
            ah[mf][3] = pack_f16(v3.x, v3.y);
        }
        const int kb = half * 8;
#pragma unroll
        for (int nf = 0; nf < 4; nf++) {
            const int col = c0 + nf * 8 + gid;
            unsigned bh[2];
            bh[0] = Wh[(kb + tig) * PW + col];
            bh[1] = Wh[(kb + tig + 4) * PW + col];
#pragma unroll
            for (int mf = 0; mf < 2; mf++) mma_f16(acc[mf][nf], ah[mf], bh);
        }
    }
}

__device__ __forceinline__ void zacc(float acc[2][4][4]) {
#pragma unroll
    for (int m = 0; m < 2; m++)
#pragma unroll
        for (int n = 0; n < 4; n++)
#pragma unroll
            for (int c = 0; c < 4; c++) acc[m][n][c] = 0.f;
}

__device__ __forceinline__ void zacc2(float acc[2][2][4]) {
#pragma unroll
    for (int m = 0; m < 2; m++)
#pragma unroll
        for (int n = 0; n < 2; n++)
#pragma unroll
            for (int c = 0; c < 4; c++) acc[m][n][c] = 0.f;
}

// ---------------- node_read kernel (R16 proven) --------------------------------
#define NR_FA0 0
#define NR_FA1 2560
#define NR_FA2 5120
#define NR_W0  7680
#define NR_W1  9856
#define NR_W2  12032
#define NR_U32 14208
#define NR_SMEM (NR_U32 * 4)

__global__ __launch_bounds__(256, 2) void node_read_kernel(
    const float* __restrict__ node_memory, const float* __restrict__ node_features,
    const float* __restrict__ b_read, float* __restrict__ out) {
    extern __shared__ unsigned su[];
    const float* fpA[3] = {(const float*)(su + NR_FA0), (const float*)(su + NR_FA1),
                           (const float*)(su + NR_FA2)};
    unsigned* const sWp[3] = {su + NR_W0, su + NR_W1, su + NR_W2};

    const int tid = threadIdx.x;
    const int lane = tid & 31;
    const int warp = tid >> 5;
    const int gid = lane >> 2;
    const int tig = lane & 3;
    const int r0 = (warp >> 2) * 32;
    const int c0 = (warp & 3) * 32;
    const int rbase = blockIdx.x * 64;

    const int arow = tid >> 2;
    const int aq = tid & 3;
    const int wkp = tid >> 4;
    const int wc8 = (tid & 15) * 8;

    const unsigned smb = (unsigned)__cvta_generic_to_shared(su);
    const unsigned faB[3] = {smb + NR_FA0 * 4, smb + NR_FA1 * 4, smb + NR_FA2 * 4};
    const unsigned whB[3] = {smb + NR_W0 * 4, smb + NR_W1 * 4, smb + NR_W2 * 4};

    auto issueA = [&](int kc) {
        const size_t row = (size_t)(rbase + arow);
        const float* base = (kc < 4)
            ? node_memory + row * D_MEM + kc * 32
            : node_features + row * D_FEAT + (kc - 4) * 32;
        const unsigned d = faB[kc % 3] + (arow * PFA + aq * 8) * 4;
        cp16(d, base + aq * 8);
        cp16(d + 16, base + aq * 8 + 4);
    };
    auto issueW = [&](int kc) {
        if (kc >= 8) return;
        const unsigned* src = g_Wf + kc * 2048 + wkp * 128 + wc8;
        const unsigned d = whB[kc % 3] + (wkp * PW + wc8) * 4;
        cp16(d, src);
        cp16(d + 16, src + 4);
    };

    issueA(0); issueW(0); CP_COMMIT();
    issueA(1); issueW(1); CP_COMMIT();

    float acc[2][4][4];
    zacc(acc);

    for (int kc = 0; kc < 8; kc++) {
        CP_WAIT1();
        __syncthreads();
        if (kc < 6) issueA(kc + 2);
        issueW(kc + 2);
        CP_COMMIT();
        if (kc < 4) {
            const float* f = fpA[kc % 3] + arow * PFA + aq * 8;
            float4 v0 = *(const float4*)f;
            float4 v1 = *(const float4*)(f + 4);
            float* o = out + (size_t)(rbase + arow) * D_MEM + kc * 32 + aq * 8;
            *(float4*)o = v0;
            *(float4*)(o + 4) = v1;
        }
        mma_k32_f32(fpA[kc % 3], sWp[kc % 3], r0, c0, gid, tig, acc);
    }

#pragma unroll
    for (int mf = 0; mf < 2; mf++) {
        const int ra = r0 + mf * 16 + gid;
#pragma unroll
        for (int nf = 0; nf < 4; nf++) {
            const int col = c0 + nf * 8 + 2 * tig;
            const int pi = col >> 1;
            const float bb0 = b_read[col], bb1 = b_read[col + 1];
            g_noderead[(size_t)(rbase + ra) * 64 + pi] =
                pack_f16(fmaxf(acc[mf][nf][0] + bb0, 0.f),
                         fmaxf(acc[mf][nf][1] + bb1, 0.f));
            g_noderead[(size_t)(rbase + ra + 8) * 64 + pi] =
                pack_f16(fmaxf(acc[mf][nf][2] + bb0, 0.f),
                         fmaxf(acc[mf][nf][3] + bb1, 0.f));
        }
    }
}

// ---------------- edge kernel (R16 proven) --------------------------------------
#define PS 116
#define STRIDE_M 132

#define E2_ST 0
#define E2_W0 7424
#define E2_W1 9600
#define E2_W2 11776
#define E2_U32 13952
#define EDGE_SMEM (E2_U32 * 4)

__device__ __forceinline__ void flush_seg(int d, int tx, const float* r, float rl) {
    float* p = g_msg_sum + (size_t)d * D_MSG + tx * 4;
    atomicAdd(p + 0, r[0]);
    atomicAdd(p + 1, r[1]);
    atomicAdd(p + 2, r[2]);
    atomicAdd(p + 3, r[3]);
    if (tx == 0) atomicAdd(&g_cnt[d], rl);
}

__global__ __launch_bounds__(256, 2) void edge_kernel(
    const float* __restrict__ edge_features, const float* __restrict__ time_encoding,
    const void* __restrict__ node_ids,
    const void* __restrict__ source_ids, const void* __restrict__ edge_ids,
    const void* __restrict__ dest_seg,
    const float* __restrict__ b_msg) {
    extern __shared__ unsigned su[];
    unsigned* sSh = su + E2_ST;
    unsigned* const sWp[3] = {su + E2_W0, su + E2_W1, su + E2_W2};
    __shared__ int s_src[64], s_eid[64], s_dst[64];

    const int tid = threadIdx.x;
    const int lane = tid & 31;
    const int warp = tid >> 5;
    const int gid = lane >> 2;
    const int tig = lane & 3;
    const int r0 = (warp >> 2) * 32;
    const int c0 = (warp & 3) * 32;
    const long long ebase = (long long)blockIdx.x * 64;

    const unsigned* nwid = (const unsigned*)node_ids;
    const int is64 = (nwid[1] == 0u && nwid[3] == 0u);

    if (tid < 64) {
        s_src[tid] = idx_at(source_ids, ebase + tid, is64);
        s_eid[tid] = idx_at(edge_ids, ebase + tid, is64);
        s_dst[tid] = idx_at(dest_seg, ebase + tid, is64);
    }
    __syncthreads();

    const int arow = tid >> 2;
    const int aq = tid & 3;
    const int wkp = tid >> 4;
    const int wc8 = (tid & 15) * 8;

    const unsigned smb = (unsigned)__cvta_generic_to_shared(su);
    const unsigned stB = smb + E2_ST * 4;
    const unsigned whB[3] = {smb + E2_W0 * 4, smb + E2_W1 * 4, smb + E2_W2 * 4};

    auto issueW = [&](int i) {
        if (i >= 7) return;
        const unsigned* src = g_Wf + (8 + i) * 2048 + wkp * 128 + wc8;
        const unsigned d = whB[i % 3] + (wkp * PW + wc8) * 4;
        cp16(d, src);
        cp16(d + 16, src + 4);
    };

    {
        const unsigned* src = g_noderead + (size_t)s_src[arow] * 64 + aq * 16;
        const unsigned d = stB + (arow * PS + aq * 16) * 4;
#pragma unroll
        for (int j = 0; j < 4; j++) cp16(d + j * 16, src + j * 4);
    }
    issueW(0);
    CP_COMMIT();
    issueW(1);
    CP_COMMIT();

    {
        const float4* ef = (const float4*)(edge_features + (size_t)s_eid[arow] * D_EDGE);
#pragma unroll
        for (int j = 0; j < 4; j++) {
            float4 v = ef[aq * 4 + j];
            const int pi = 64 + aq * 8 + 2 * j;
            sSh[arow * PS + pi] = pack_f16(v.x, v.y);
            sSh[arow * PS + pi + 1] = pack_f16(v.z, v.w);
        }
        const float4* tf = (const float4*)(time_encoding + (ebase + arow) * D_TIME);
#pragma unroll
        for (int j = 0; j < 2; j++) {
            float4 v = tf[aq * 2 + j];
            const int pi = 96 + aq * 4 + 2 * j;
            sSh[arow * PS + pi] = pack_f16(v.x, v.y);
            sSh[arow * PS + pi + 1] = pack_f16(v.z, v.w);
        }
    }

    float acc[2][4][4];
    zacc(acc);

    for (int kc = 0; kc < 7; kc++) {
        CP_WAIT1();
        __syncthreads();
        issueW(kc + 2);
        CP_COMMIT();
        mma_k32(sSh + kc * 16, PS, sWp[kc % 3], r0, c0, gid, tig, acc);
    }
    __syncthreads();

    float* msg = (float*)su;
#pragma unroll
    for (int mf = 0; mf < 2; mf++) {
        const int ra = r0 + mf * 16 + gid;
#pragma unroll
        for (int nf = 0; nf < 4; nf++) {
            const int col = c0 + nf * 8 + 2 * tig;
            const float b0 = b_msg[col], b1 = b_msg[col + 1];
            msg[ra * STRIDE_M + col]           = fmaxf(acc[mf][nf][0] + b0, 0.f);
            msg[ra * STRIDE_M + col + 1]       = fmaxf(acc[mf][nf][1] + b1, 0.f);
            msg[(ra + 8) * STRIDE_M + col]     = fmaxf(acc[mf][nf][2] + b0, 0.f);
            msg[(ra + 8) * STRIDE_M + col + 1] = fmaxf(acc[mf][nf][3] + b1, 0.f);
        }
    }
    __syncthreads();

    {
        const int tx = lane;
        const int e0 = warp * 8;
        int curd = s_dst[e0];
        float r[4] = {0.f, 0.f, 0.f, 0.f};
        float rl = 0.f;
#pragma unroll
        for (int i = 0; i < 8; i++) {
            const int e = e0 + i;
            const int d = s_dst[e];
            const float4 v = *(const float4*)(msg + e * STRIDE_M + tx * 4);
            if (d != curd) {
                flush_seg(curd, tx, r, rl);
                curd = d;
                r[0] = r[1] = r[2] = r[3] = 0.f;
                rl = 0.f;
            }
            r[0] += v.x; r[1] += v.y; r[2] += v.z; r[3] += v.w;
            rl += 1.f;
        }
        flush_seg(curd, tx, r, rl);
    }
}

// ---------------- dest kernel: 32-row tiles, 256 blocks, 2 CTAs/SM ------------
#define DPS 132
#define DPD 68

#define D3_W0 0
#define D3_W1 2176
#define D3_W2 4352
#define D3_S  6528     // sS: 32*132 = 4224
#define D3_D  10752    // sD2: 32*68 = 2176
#define DEST_U32 12928
#define DEST_SMEM (DEST_U32 * 4)   // 51712 B -> 2 CTAs/SM

__global__ __launch_bounds__(256, 2) void dest_kernel(
    const void* __restrict__ node_ids,
    const float* __restrict__ b_agg, const float* __restrict__ b_upd,
    const float* __restrict__ b_write, float* __restrict__ out) {
    extern __shared__ unsigned su[];
    unsigned* const sWp[3] = {su + D3_W0, su + D3_W1, su + D3_W2};
    unsigned* sS = su + D3_S;
    unsigned* sD2 = su + D3_D;
    __shared__ int s_nid[32];

    const int tid = threadIdx.x;
    const int lane = tid & 31;
    const int warp = tid >> 5;
    const int gid = lane >> 2;
    const int tig = lane & 3;
    const int c0 = warp * 16;     // 8 warps x 16 cols
    const int rbase = blockIdx.x * 32;

    const unsigned* nwid = (const unsigned*)node_ids;
    const int is64 = (nwid[1] == 0u && nwid[3] == 0u);

    if (tid < 32) s_nid[tid] = idx_at(node_ids, rbase + tid, is64);
    __syncthreads();

    const int arow = tid >> 3;    // 0..31
    const int aq = tid & 7;       // 0..7 (8 u32 each)
    const int wkp = tid >> 4;
    const int wc8 = (tid & 15) * 8;

    const unsigned smb = (unsigned)__cvta_generic_to_shared(su);
    const unsigned sSB = smb + D3_S * 4;
    const unsigned whB[3] = {smb + D3_W0 * 4, smb + D3_W1 * 4, smb + D3_W2 * 4};

    auto issueW = [&](int i) {   // seq chunk i (0..19) -> g_Wf chunk 15+i
        if (i >= 20) return;
        const unsigned* src = g_Wf + (15 + i) * 2048 + wkp * 128 + wc8;
        const unsigned d = whB[i % 3] + (wkp * PW + wc8) * 4;
        cp16(d, src);
        cp16(d + 16, src + 4);
    };

    // prologue group 0: dst_read row gather (pre-packed fp16) + W chunk 0
    {
        const unsigned* src = g_noderead + (size_t)s_nid[arow] * 64 + aq * 8;
        const unsigned d = sSB + (arow * DPS + aq * 8) * 4;
        cp16(d, src);
        cp16(d + 16, src + 4);
    }
    issueW(0);
    CP_COMMIT();
    issueW(1);
    CP_COMMIT();

    CP_WAIT1();        // group 0 (gather + W0) landed
    __syncthreads();

    // copy dst_read sS -> sD2 (32 x 64 u32; 8 u32 per thread)
    {
        const int row = tid >> 3;
        const int pi = (tid & 7) * 8;
        *(uint4*)(sD2 + row * DPD + pi) = *(const uint4*)(sS + row * DPS + pi);
        *(uint4*)(sD2 + row * DPD + pi + 4) = *(const uint4*)(sS + row * DPS + pi + 4);
    }
    // msg_mean -> sS kp[64,128); re-zero scratch (16 floats = 8 kp per thread)
    {
        const int dg = rbase + arow;
        const float inv = 1.0f / fmaxf(g_cnt[dg], 1.0f);
        const float4* sp = (const float4*)(g_msg_sum + (size_t)dg * D_MSG + aq * 16);
#pragma unroll
        for (int j4 = 0; j4 < 4; j4++) {
            float4 v = sp[j4];
            const int pi = 64 + aq * 8 + 2 * j4;
            sS[arow * DPS + pi] = pack_f16(v.x * inv, v.y * inv);
            sS[arow * DPS + pi + 1] = pack_f16(v.z * inv, v.w * inv);
        }
        float4 z = {0.f, 0.f, 0.f, 0.f};
        float4* p = (float4*)(g_msg_sum + (size_t)dg * D_MSG + aq * 16);
#pragma unroll
        for (int j4 = 0; j4 < 4; j4++) p[j4] = z;
        if (aq == 0) g_cnt[dg] = 0.f;
    }
    __syncthreads();

    float acc[2][2][4];

    // ---- GEMM agg: K=256 (seq chunks 0-7) ----
    zacc2(acc);
    for (int kc = 0; kc < 8; kc++) {
        CP_WAIT1();
        __syncthreads();
        issueW(kc + 2);
        CP_COMMIT();
        mma_k32_n16(sS + kc * 16, DPS, sWp[kc % 3], c0, gid, tig, acc);
    }
    __syncthreads();
#pragma unroll
    for (int mf = 0; mf < 2; mf++) {
        const int ra = mf * 16 + gid;
#pragma unroll
        for (int nf = 0; nf < 2; nf++) {
            const int col = c0 + nf * 8 + 2 * tig;
            const int pi = col >> 1;
            const float bb0 = b_agg[col], bb1 = b_agg[col + 1];
            sS[ra * DPS + pi] = pack_f16(fmaxf(acc[mf][nf][0] + bb0, 0.f),
                                         fmaxf(acc[mf][nf][1] + bb1, 0.f));
            sS[(ra + 8) * DPS + pi] = pack_f16(fmaxf(acc[mf][nf][2] + bb0, 0.f),
                                               fmaxf(acc[mf][nf][3] + bb1, 0.f));
        }
    }

    // ---- GEMM upd: K=256 (seq chunks 8-15; agg from sS, dst_read from sD2) ----
    zacc2(acc);
    for (int kc = 0; kc < 8; kc++) {
        const int i = 8 + kc;
        CP_WAIT1();
        __syncthreads();   // kc=0: orders agg epilogue for all warps
        issueW(i + 2);
        CP_COMMIT();
        if (kc < 4)
            mma_k32_n16(sS + kc * 16, DPS, sWp[i % 3], c0, gid, tig, acc);
        else
            mma_k32_n16(sD2 + (kc - 4) * 16, DPD, sWp[i % 3], c0, gid, tig, acc);
    }
    __syncthreads();
#pragma unroll
    for (int mf = 0; mf < 2; mf++) {
        const int ra = mf * 16 + gid;
#pragma unroll
        for (int nf = 0; nf < 2; nf++) {
            const int col = c0 + nf * 8 + 2 * tig;
            const int pi = col >> 1;
            const float bb0 = b_upd[col], bb1 = b_upd[col + 1];
            sS[ra * DPS + pi] = pack_f16(fmaxf(acc[mf][nf][0] + bb0, 0.f),
                                         fmaxf(acc[mf][nf][1] + bb1, 0.f));
            sS[(ra + 8) * DPS + pi] = pack_f16(fmaxf(acc[mf][nf][2] + bb0, 0.f),
                                               fmaxf(acc[mf][nf][3] + bb1, 0.f));
        }
    }

    // ---- GEMM write: K=128 (seq chunks 16-19); tanh + scatter ----
    zacc2(acc);
    for (int kc = 0; kc < 4; kc++) {
        const int i = 16 + kc;
        CP_WAIT1();
        __syncthreads();
        issueW(i + 2);     // no-op for i+2 >= 20
        CP_COMMIT();
        mma_k32_n16(sS + kc * 16, DPS, sWp[i % 3], c0, gid, tig, acc);
    }
#pragma unroll
    for (int mf = 0; mf < 2; mf++) {
        const int ra = mf * 16 + gid;
        const int n0 = s_nid[ra], n1 = s_nid[ra + 8];
#pragma unroll
        for (int nf = 0; nf < 2; nf++) {
            const int col = c0 + nf * 8 + 2 * tig;
            const float bb0 = b_write[col], bb1 = b_write[col + 1];
            float2 o0, o1;
            o0.x = tanhf(acc[mf][nf][0] + bb0);
            o0.y = tanhf(acc[mf][nf][1] + bb1);
            o1.x = tanhf(acc[mf][nf][2] + bb0);
            o1.y = tanhf(acc[mf][nf][3] + bb1);
            *(float2*)(out + (size_t)n0 * D_MEM + col) = o0;
            *(float2*)(out + (size_t)n1 * D_MEM + col) = o1;
        }
    }
}

// ---------------- launch ------------------------------------------------------
extern "C" void kernel_launch(void* const* d_in, const int* in_sizes, int n_in,
                              void* d_out, int out_size) {
    const float* node_memory   = (const float*)d_in[0];
    const float* node_features = (const float*)d_in[1];
    const float* edge_features = (const float*)d_in[2];
    const float* time_encoding = (const float*)d_in[3];
    const void*  node_ids      = d_in[4];
    const void*  source_ids    = d_in[5];
    const void*  edge_ids      = d_in[6];
    const void*  dest_seg      = d_in[7];
    const float* W_read  = (const float*)d_in[8];
    const float* b_read  = (const float*)d_in[9];
    const float* W_msg   = (const float*)d_in[10];
    const float* b_msg   = (const float*)d_in[11];
    const float* W_agg   = (const float*)d_in[12];
    const float* b_agg   = (const float*)d_in[13];
    const float* W_upd   = (const float*)d_in[14];
    const float* b_upd   = (const float*)d_in[15];
    const float* W_write = (const float*)d_in[16];
    const float* b_write = (const float*)d_in[17];
    float* out = (float*)d_out;

    cudaFuncSetAttribute(node_read_kernel, cudaFuncAttributeMaxDynamicSharedMemorySize, NR_SMEM);
    cudaFuncSetAttribute(edge_kernel, cudaFuncAttributeMaxDynamicSharedMemorySize, EDGE_SMEM);
    cudaFuncSetAttribute(dest_kernel, cudaFuncAttributeMaxDynamicSharedMemorySize, DEST_SMEM);

    prep_kernel<<<280, 256>>>(W_read, W_msg, W_agg, W_upd, W_write);

    node_read_kernel<<<N_NODES / 64, 256, NR_SMEM>>>(
        node_memory, node_features, b_read, out);

    edge_kernel<<<N_EDGE / 64, 256, EDGE_SMEM>>>(
        edge_features, time_encoding, node_ids,
        source_ids, edge_ids, dest_seg, b_msg);

    dest_kernel<<<N_DEST / 32, 256, DEST_SMEM>>>(
        node_ids, b_agg, b_upd, b_write, out);
}